// round 8
// baseline (speedup 1.0000x reference)
#include <cuda_runtime.h>
#include <cstdint>

#define T_LEN 131072
#define HALF_T (T_LEN / 2)
#define D_X 16
#define D_L 8

// d_out layout (flat concat of reference tuple, all float32)
#define OFF_RECON 0
#define OFF_PRED  (T_LEN * D_X)
#define OFF_LMP   (2 * T_LEN * D_X)
#define OFF_LVP   (OFF_LMP + 2 * T_LEN * D_L)
#define OFF_CT    (OFF_LVP + 2 * T_LEN * D_L)
#define OFF_CT1   (OFF_CT + T_LEN * D_X * D_L)

typedef unsigned long long u64;

// ---------------------------------------------------------------------------
// Packed fp32x2 ops on u64-carried pairs (no per-op MOV packing).
// ---------------------------------------------------------------------------
__device__ __forceinline__ u64 pk2(float x, float y) {
    u64 r;
    asm("mov.b64 %0, {%1, %2};" : "=l"(r) : "f"(x), "f"(y));
    return r;
}
__device__ __forceinline__ void upk2(u64 a, float& x, float& y) {
    asm("mov.b64 {%0, %1}, %2;" : "=f"(x), "=f"(y) : "l"(a));
}
__device__ __forceinline__ u64 ffma2u(u64 a, u64 b, u64 c) {
    u64 d;
    asm("fma.rn.f32x2 %0, %1, %2, %3;" : "=l"(d) : "l"(a), "l"(b), "l"(c));
    return d;
}
__device__ __forceinline__ u64 fmul2u(u64 a, u64 b) {
    u64 d;
    asm("mul.rn.f32x2 %0, %1, %2;" : "=l"(d) : "l"(a), "l"(b));
    return d;
}
__device__ __forceinline__ u64 fadd2u(u64 a, u64 b) {
    u64 d;
    asm("add.rn.f32x2 %0, %1, %2;" : "=l"(d) : "l"(a), "l"(b));
    return d;
}

// ---------------------------------------------------------------------------
// Preprocessed decoder weights (device-global scratch; no allocation).
// ---------------------------------------------------------------------------
__device__ __align__(16) float g_w0t[D_X * 64 * 32];  // [n][j][f]
__device__ __align__(16) float g_w12[D_X * 64];       // collapsed lw1@lw2
__device__ __align__(16) float g_beff[D_X];           // lb1@lw2 + lb2

__global__ void prep_kernel(const float* __restrict__ lw0,
                            const float* __restrict__ lw1,
                            const float* __restrict__ lw2,
                            const float* __restrict__ lb0,
                            const float* __restrict__ lb1,
                            const float* __restrict__ lb2,
                            float* __restrict__ out) {
    int tid = threadIdx.x;          // 1024 threads: (n, j)
    int n = tid >> 6;
    int j = tid & 63;
#pragma unroll
    for (int f = 0; f < 32; f++)
        g_w0t[(n * 64 + j) * 32 + f] = lw0[(n * 32 + f) * 64 + j];
    float acc = 0.f;
#pragma unroll 8
    for (int o = 0; o < 64; o++)
        acc = fmaf(lw1[(n * 64 + j) * 64 + o], lw2[n * 64 + o], acc);
    g_w12[n * 64 + j] = acc;
    if (j == 0) {
        float b = lb2[n];
        for (int o = 0; o < 64; o++)
            b = fmaf(lb1[n * 64 + o], lw2[n * 64 + o], b);
        g_beff[n] = b;
    }
    __syncthreads();
    // pred[0]: features are all-zero -> h = relu(lb0), out = relu(h.w12 + beff)
    if (j == 0) {
        float s = g_beff[n];
        for (int o = 0; o < 64; o++) {
            float h = fmaxf(lb0[n * 64 + o], 0.f);
            s = fmaf(h, g_w12[n * 64 + o], s);
        }
        out[OFF_PRED + n] = fmaxf(s, 0.f);
    }
}

// ---------------------------------------------------------------------------
// enc layers 0+1 (packed block: w0[8] b0[8] w1[64] b1[8]) -> h1[8]
// ---------------------------------------------------------------------------
__device__ __forceinline__ void enc01(float s, const float* __restrict__ w,
                                      float* __restrict__ h1) {
    float h0[8];
#pragma unroll
    for (int i = 0; i < 8; i++) {
        float v = fmaf(s, w[i], w[8 + i]);
        h0[i] = v > 0.f ? v : 0.01f * v;
    }
#pragma unroll
    for (int j = 0; j < 8; j++) {
        float a = 0.f;
#pragma unroll
        for (int i = 0; i < 8; i++) a = fmaf(h0[i], w[16 + i * 8 + j], a);
        a += w[80 + j];
        h1[j] = a > 0.f ? a : 0.01f * a;
    }
}

// a = 0; fmaf i=0..7 ascending (round-4 order; bias handled by caller)
__device__ __forceinline__ float dot8z(const float* __restrict__ h,
                                       float4 a4, float4 b4) {
    float a = 0.f;
    a = fmaf(h[0], a4.x, a); a = fmaf(h[1], a4.y, a);
    a = fmaf(h[2], a4.z, a); a = fmaf(h[3], a4.w, a);
    a = fmaf(h[4], b4.x, a); a = fmaf(h[5], b4.y, a);
    a = fmaf(h[6], b4.z, a); a = fmaf(h[7], b4.w, a);
    return a;
}

// ---------------------------------------------------------------------------
// Paired head: two rows sharing every weight load; round-4 arithmetic order.
// ---------------------------------------------------------------------------
__device__ __forceinline__ void head_fn2(const float* __restrict__ xa8,
                                         const float* __restrict__ xb8,
                                         const float* __restrict__ w1t,
                                         const float* __restrict__ b1,
                                         const float* __restrict__ w2,
                                         const float* __restrict__ b2,
                                         float* __restrict__ dsta,
                                         float* __restrict__ dstb) {
    const ulonglong2* xap = (const ulonglong2*)xa8;
    const ulonglong2* xbp = (const ulonglong2*)xb8;
    ulonglong2 xa01 = xap[0], xa23 = xap[1];
    ulonglong2 xb01 = xbp[0], xb23 = xbp[1];
    // output accumulators seeded with b2 (round-4: o = b2 pairs)
    const ulonglong2* b2p = (const ulonglong2*)b2;
    ulonglong2 b2lo = b2p[0], b2hi = b2p[1];
    u64 oa0 = b2lo.x, oa1 = b2lo.y, oa2 = b2hi.x, oa3 = b2hi.y;
    u64 ob0 = oa0, ob1 = oa1, ob2 = oa2, ob3 = oa3;
    const ulonglong2* w1p = (const ulonglong2*)w1t;
    const ulonglong2* w2p = (const ulonglong2*)w2;
#pragma unroll 4
    for (int j = 0; j < 128; j++) {
        ulonglong2 wA = w1p[j * 2];      // (w0,w1),(w2,w3)
        ulonglong2 wB = w1p[j * 2 + 1];  // (w4,w5),(w6,w7)
        float bj = b1[j];
        // round-4 order: a0 = x01*wA01; a1 = x45*wB01; a0 += x23*wA23; a1 += x67*wB23
        u64 a0 = ffma2u(xa01.x, wA.x, 0ull);
        u64 a1 = ffma2u(xa23.x, wB.x, 0ull);
        a0 = ffma2u(xa01.y, wA.y, a0);
        a1 = ffma2u(xa23.y, wB.y, a1);
        u64 c0 = ffma2u(xb01.x, wA.x, 0ull);
        u64 c1 = ffma2u(xb23.x, wB.x, 0ull);
        c0 = ffma2u(xb01.y, wA.y, c0);
        c1 = ffma2u(xb23.y, wB.y, c1);
        float a0x, a0y, a1x, a1y, c0x, c0y, c1x, c1y;
        upk2(a0, a0x, a0y); upk2(a1, a1x, a1y);
        upk2(c0, c0x, c0y); upk2(c1, c1x, c1y);
        float ha = a0x + a0y + a1x + a1y + bj;   // left-assoc as round 4
        float hb = c0x + c0y + c1x + c1y + bj;
        ha = fmaxf(ha, 0.f);
        hb = fmaxf(hb, 0.f);
        u64 hha = pk2(ha, ha);
        u64 hhb = pk2(hb, hb);
        ulonglong2 u = w2p[j * 2];
        ulonglong2 v = w2p[j * 2 + 1];
        oa0 = ffma2u(hha, u.x, oa0); oa1 = ffma2u(hha, u.y, oa1);
        oa2 = ffma2u(hha, v.x, oa2); oa3 = ffma2u(hha, v.y, oa3);
        ob0 = ffma2u(hhb, u.x, ob0); ob1 = ffma2u(hhb, u.y, ob1);
        ob2 = ffma2u(hhb, v.x, ob2); ob3 = ffma2u(hhb, v.y, ob3);
    }
    ulonglong2* da = (ulonglong2*)dsta;
    ulonglong2* db = (ulonglong2*)dstb;
    da[0] = make_ulonglong2(oa0, oa1);
    da[1] = make_ulonglong2(oa2, oa3);
    db[0] = make_ulonglong2(ob0, ob1);
    db[1] = make_ulonglong2(ob2, ob3);
}

// ---------------------------------------------------------------------------
// Mega kernel: thread handles TWO timesteps (t0, t1 = t0 + T/2) so every
// decoder weight load feeds 8 FFMA2 (R,P x t0,t1). blockIdx.y = quarter
// (nodes 4q..4q+3; head-row pair q).
// ---------------------------------------------------------------------------
#define BS 352
#define GX ((HALF_T + BS - 1) / BS)   // 187

// smem float offsets
#define S_W0    0                    // 4*64*32 = 8192
#define S_BW    8192                 // [ln][j] (b0, w12) pairs: 512
#define S_BEFF  8704                 // 4
#define S_CL01  8708                 // 88
#define S_PL01  8796                 // 88
#define S_CW2T  8884                 // [ln][k][i] 256
#define S_CB2   9140                 // 32
#define S_PW2T  9172                 // 256
#define S_PB2   9428                 // 32
#define S_HW1T  9460                 // 1024
#define S_HB1   10484                // 128
#define S_HW2   10612                // 1024
#define S_HB2   11636                // 8
#define S_TOT   11648
#define MEGA_SMEM_BYTES (S_TOT * 4)  // ~46.6 KB

__global__ __launch_bounds__(BS, 1)
void mega_kernel(const float* __restrict__ lm, const float* __restrict__ lv,
                 const float* __restrict__ Tin,
                 const float* cw0, const float* cb0, const float* cw1,
                 const float* cb1, const float* cw2, const float* cb2,
                 const float* pw0, const float* pb0, const float* pw1,
                 const float* pb1, const float* pw2, const float* pb2,
                 const float* fmw1, const float* fmb1,
                 const float* fmw2, const float* fmb2,
                 const float* fvw1, const float* fvb1,
                 const float* fvw2, const float* fvb2,
                 const float* __restrict__ lb0,
                 float* __restrict__ out) {
    extern __shared__ __align__(16) float smem[];
    const int tid = threadIdx.x;
    const int q = blockIdx.y;
    const int nb = q * 4;             // node base

    // ---- cooperative smem fill ----
    for (int i = tid; i < (4 * 64 * 32) / 4; i += BS)
        ((float4*)(smem + S_W0))[i] = ((const float4*)(g_w0t + nb * 2048))[i];
    for (int i = tid; i < 256; i += BS) {
        smem[S_BW + 2 * i]     = lb0[nb * 64 + i];
        smem[S_BW + 2 * i + 1] = g_w12[nb * 64 + i];
    }
    if (tid < 4) smem[S_BEFF + tid] = g_beff[nb + tid];
    for (int i = tid; i < 88; i += BS) {
        float v, u;
        if (i < 8)       { v = cw0[i];      u = pw0[i];      }
        else if (i < 16) { v = cb0[i - 8];  u = pb0[i - 8];  }
        else if (i < 80) { v = cw1[i - 16]; u = pw1[i - 16]; }
        else             { v = cb1[i - 80]; u = pb1[i - 80]; }
        smem[S_CL01 + i] = v;
        smem[S_PL01 + i] = u;
    }
    for (int i = tid; i < 256; i += BS) {
        int ln = i >> 6, k = (i >> 3) & 7, ii = i & 7;
        int src = ii * 128 + (nb + ln) * 8 + k;
        smem[S_CW2T + i] = cw2[src];
        smem[S_PW2T + i] = pw2[src];
    }
    for (int i = tid; i < 32; i += BS) {
        smem[S_CB2 + i] = cb2[nb * 8 + i];
        smem[S_PB2 + i] = pb2[nb * 8 + i];
    }
    {
        const float* hw1 = (q >> 1) ? fvw1 : fmw1;
        const float* hw2 = (q >> 1) ? fvw2 : fmw2;
        const float* hb1 = (q >> 1) ? fvb1 : fmb1;
        const float* hb2 = (q >> 1) ? fvb2 : fmb2;
        for (int i = tid; i < 1024; i += BS) {
            int j = i >> 3, k = i & 7;
            smem[S_HW1T + i] = hw1[k * 128 + j];
            smem[S_HW2 + i]  = hw2[i];
        }
        if (tid < 128) smem[S_HB1 + tid] = hb1[tid];
        if (tid < 8)   smem[S_HB2 + tid] = hb2[tid];
    }
    __syncthreads();

    const int tb = blockIdx.x * BS + tid;
    if (tb >= HALF_T) return;
    const size_t t0 = (size_t)tb;
    const size_t t1 = (size_t)tb + HALF_T;

    // ---- enc phase for both timesteps (round-4 exact fp orders) ----
    unsigned mask0 = 0, mask1 = 0;    // 4 node-bytes each
    {
        float sA = Tin[t0];
        float sB = Tin[t1];
        float h1a[8], h1b[8];
        enc01(sA, smem + S_CL01, h1a);
        enc01(sB, smem + S_CL01, h1b);
        float* dA = out + OFF_CT + t0 * 128 + nb * 8;
        float* dB = out + OFF_CT + t1 * 128 + nb * 8;
#pragma unroll
        for (int ln = 0; ln < 4; ln++) {
            float va[8], vb[8];
#pragma unroll
            for (int k = 0; k < 8; k++) {
                const float4* w4 = (const float4*)(smem + S_CW2T + (ln * 8 + k) * 8);
                float4 wa = w4[0], wb = w4[1];
                float bia = smem[S_CB2 + ln * 8 + k];
                float aA = dot8z(h1a, wa, wb) + bia;   // bias-last (round 4)
                float aB = dot8z(h1b, wa, wb) + bia;
                bool onA = !(aA < 0.1f);
                bool onB = !(aB < 0.1f);
                va[k] = onA ? 1.f : 0.f;
                vb[k] = onB ? 1.f : 0.f;
                if (onA) mask0 |= 1u << (ln * 8 + k);
                if (onB) mask1 |= 1u << (ln * 8 + k);
            }
            *(float4*)&dA[ln * 8]     = make_float4(va[0], va[1], va[2], va[3]);
            *(float4*)&dA[ln * 8 + 4] = make_float4(va[4], va[5], va[6], va[7]);
            *(float4*)&dB[ln * 8]     = make_float4(vb[0], vb[1], vb[2], vb[3]);
            *(float4*)&dB[ln * 8 + 4] = make_float4(vb[4], vb[5], vb[6], vb[7]);
        }
        // continuous Ct_1 for t0 and t1
        enc01(sA, smem + S_PL01, h1a);
        enc01(sB, smem + S_PL01, h1b);
        dA = out + OFF_CT1 + t0 * 128 + nb * 8;
        dB = out + OFF_CT1 + t1 * 128 + nb * 8;
#pragma unroll
        for (int ln = 0; ln < 4; ln++) {
            float va[8], vb[8];
#pragma unroll
            for (int k = 0; k < 8; k++) {
                const float4* w4 = (const float4*)(smem + S_PW2T + (ln * 8 + k) * 8);
                float4 wa = w4[0], wb = w4[1];
                float bia = smem[S_PB2 + ln * 8 + k];
                va[k] = dot8z(h1a, wa, wb) + bia;
                vb[k] = dot8z(h1b, wa, wb) + bia;
            }
            *(float4*)&dA[ln * 8]     = make_float4(va[0], va[1], va[2], va[3]);
            *(float4*)&dA[ln * 8 + 4] = make_float4(va[4], va[5], va[6], va[7]);
            *(float4*)&dB[ln * 8]     = make_float4(vb[0], vb[1], vb[2], vb[3]);
            *(float4*)&dB[ln * 8 + 4] = make_float4(vb[4], vb[5], vb[6], vb[7]);
        }
    }
    const bool hasP1 = (t1 + 1 < T_LEN);
    float h1p0[8], h1p1[8];
    enc01(Tin[t0 + 1], smem + S_PL01, h1p0);
    {
        float s2 = hasP1 ? Tin[t1 + 1] : 0.f;
        enc01(s2, smem + S_PL01, h1p1);
    }

    // ---- head phase: quarter q handles row pair (rb+t0, rb+t1) ----
    {
        const float* x = (q >> 1) ? lv : lm;
        float* hdst = out + ((q >> 1) ? OFF_LVP : OFF_LMP);
        size_t rb = (q & 1) ? (size_t)T_LEN : 0;
        head_fn2(x + (rb + t0) * 8, x + (rb + t1) * 8,
                 smem + S_HW1T, smem + S_HB1, smem + S_HW2, smem + S_HB2,
                 hdst + (rb + t0) * 8, hdst + (rb + t1) * 8);
    }

    // ---- decode: per node, u64-packed features for both t's, one j-loop ----
    const float4* lm4 = (const float4*)lm;
    const float4* lv4 = (const float4*)lv;

    for (int ln = 0; ln < 4; ln++) {
        u64 fR0[16], fP0[16], fR1[16], fP1[16];
        // build t0
        {
            float Ma[8], Mb[8], Va[8], Vb[8];
            *(float4*)&Ma[0] = lm4[t0 * 2];
            *(float4*)&Ma[4] = lm4[t0 * 2 + 1];
            *(float4*)&Mb[0] = lm4[((size_t)T_LEN + t0) * 2];
            *(float4*)&Mb[4] = lm4[((size_t)T_LEN + t0) * 2 + 1];
            *(float4*)&Va[0] = lv4[t0 * 2];
            *(float4*)&Va[4] = lv4[t0 * 2 + 1];
            *(float4*)&Vb[0] = lv4[((size_t)T_LEN + t0) * 2];
            *(float4*)&Vb[4] = lv4[((size_t)T_LEN + t0) * 2 + 1];
            unsigned byte0 = (mask0 >> (ln * 8)) & 0xffu;
#pragma unroll
            for (int k = 0; k < 8; k++) {
                const float4* w4p = (const float4*)(smem + S_PW2T + (ln * 8 + k) * 8);
                float4 wa = w4p[0], wb = w4p[1];
                float cp = smem[S_PB2 + ln * 8 + k];   // bias-first (round 4)
                cp = fmaf(h1p0[0], wa.x, cp); cp = fmaf(h1p0[1], wa.y, cp);
                cp = fmaf(h1p0[2], wa.z, cp); cp = fmaf(h1p0[3], wa.w, cp);
                cp = fmaf(h1p0[4], wb.x, cp); cp = fmaf(h1p0[5], wb.y, cp);
                cp = fmaf(h1p0[6], wb.z, cp); cp = fmaf(h1p0[7], wb.w, cp);
                u64 cp2 = pk2(cp, cp);
                u64 Mk = pk2(Ma[k], Mb[k]);
                u64 Vk = pk2(Va[k], Vb[k]);
                bool on = (byte0 >> k) & 1u;
                fR0[k]     = on ? Mk : 0ull;
                fR0[8 + k] = on ? Vk : 0ull;
                fP0[k]     = fmul2u(cp2, Mk);
                fP0[8 + k] = fmul2u(cp2, Vk);
            }
        }
        // build t1
        {
            float Ma[8], Mb[8], Va[8], Vb[8];
            *(float4*)&Ma[0] = lm4[t1 * 2];
            *(float4*)&Ma[4] = lm4[t1 * 2 + 1];
            *(float4*)&Mb[0] = lm4[((size_t)T_LEN + t1) * 2];
            *(float4*)&Mb[4] = lm4[((size_t)T_LEN + t1) * 2 + 1];
            *(float4*)&Va[0] = lv4[t1 * 2];
            *(float4*)&Va[4] = lv4[t1 * 2 + 1];
            *(float4*)&Vb[0] = lv4[((size_t)T_LEN + t1) * 2];
            *(float4*)&Vb[4] = lv4[((size_t)T_LEN + t1) * 2 + 1];
            unsigned byte1 = (mask1 >> (ln * 8)) & 0xffu;
#pragma unroll
            for (int k = 0; k < 8; k++) {
                const float4* w4p = (const float4*)(smem + S_PW2T + (ln * 8 + k) * 8);
                float4 wa = w4p[0], wb = w4p[1];
                float cp = smem[S_PB2 + ln * 8 + k];
                cp = fmaf(h1p1[0], wa.x, cp); cp = fmaf(h1p1[1], wa.y, cp);
                cp = fmaf(h1p1[2], wa.z, cp); cp = fmaf(h1p1[3], wa.w, cp);
                cp = fmaf(h1p1[4], wb.x, cp); cp = fmaf(h1p1[5], wb.y, cp);
                cp = fmaf(h1p1[6], wb.z, cp); cp = fmaf(h1p1[7], wb.w, cp);
                u64 cp2 = pk2(cp, cp);
                u64 Mk = pk2(Ma[k], Mb[k]);
                u64 Vk = pk2(Va[k], Vb[k]);
                bool on = (byte1 >> k) & 1u;
                fR1[k]     = on ? Mk : 0ull;
                fR1[8 + k] = on ? Vk : 0ull;
                fP1[k]     = fmul2u(cp2, Mk);
                fP1[8 + k] = fmul2u(cp2, Vk);
            }
        }

        float outR0 = 0.f, outP0 = 0.f, outR1 = 0.f, outP1 = 0.f;
        const ulonglong2* wbase = (const ulonglong2*)(smem + S_W0 + ln * 2048);
        const float2* bw = (const float2*)(smem + S_BW + 2 * ln * 64);
#pragma unroll 2
        for (int j = 0; j < 64; j++) {
            // each j-row is 32 floats = 128 B = 8 ulonglong2:
            // M half = wv[0..3] (features 0..15), V half = wv[4..7] (16..31)
            const ulonglong2* wv = wbase + j * 8;
            u64 aR0 = 0ull, bR0 = 0ull, aP0 = 0ull, bP0 = 0ull;
            u64 aR1 = 0ull, bR1 = 0ull, aP1 = 0ull, bP1 = 0ull;
#pragma unroll
            for (int m = 0; m < 4; m++) {
                ulonglong2 wq = wv[m];           // weight pairs 2m, 2m+1 (M half)
                aR0 = ffma2u(fR0[2 * m],     wq.x, aR0);
                bR0 = ffma2u(fR0[2 * m + 1], wq.y, bR0);
                aP0 = ffma2u(fP0[2 * m],     wq.x, aP0);
                bP0 = ffma2u(fP0[2 * m + 1], wq.y, bP0);
                aR1 = ffma2u(fR1[2 * m],     wq.x, aR1);
                bR1 = ffma2u(fR1[2 * m + 1], wq.y, bR1);
                aP1 = ffma2u(fP1[2 * m],     wq.x, aP1);
                bP1 = ffma2u(fP1[2 * m + 1], wq.y, bP1);
            }
#pragma unroll
            for (int m = 0; m < 4; m++) {
                ulonglong2 wq = wv[4 + m];       // V half
                aR0 = ffma2u(fR0[8 + 2 * m], wq.x, aR0);
                bR0 = ffma2u(fR0[9 + 2 * m], wq.y, bR0);
                aP0 = ffma2u(fP0[8 + 2 * m], wq.x, aP0);
                bP0 = ffma2u(fP0[9 + 2 * m], wq.y, bP0);
                aR1 = ffma2u(fR1[8 + 2 * m], wq.x, aR1);
                bR1 = ffma2u(fR1[9 + 2 * m], wq.y, bR1);
                aP1 = ffma2u(fP1[8 + 2 * m], wq.x, aP1);
                bP1 = ffma2u(fP1[9 + 2 * m], wq.y, bP1);
            }
            float2 bwj = bw[j];
            float x, y;
            u64 s;
            s = fadd2u(aR0, bR0); upk2(s, x, y);
            float hR0 = fmaxf(x + y + bwj.x, 0.f);
            s = fadd2u(aP0, bP0); upk2(s, x, y);
            float hP0 = fmaxf(x + y + bwj.x, 0.f);
            s = fadd2u(aR1, bR1); upk2(s, x, y);
            float hR1 = fmaxf(x + y + bwj.x, 0.f);
            s = fadd2u(aP1, bP1); upk2(s, x, y);
            float hP1 = fmaxf(x + y + bwj.x, 0.f);
            outR0 = fmaf(hR0, bwj.y, outR0);
            outP0 = fmaf(hP0, bwj.y, outP0);
            outR1 = fmaf(hR1, bwj.y, outR1);
            outP1 = fmaf(hP1, bwj.y, outP1);
        }
        float be = smem[S_BEFF + ln];
        out[OFF_RECON + t0 * 16 + nb + ln] = fmaxf(outR0 + be, 0.f);
        out[OFF_RECON + t1 * 16 + nb + ln] = fmaxf(outR1 + be, 0.f);
        out[OFF_PRED + (t0 + 1) * 16 + nb + ln] = fmaxf(outP0 + be, 0.f);
        if (hasP1)
            out[OFF_PRED + (t1 + 1) * 16 + nb + ln] = fmaxf(outP1 + be, 0.f);
    }
}

// ---------------------------------------------------------------------------
extern "C" void kernel_launch(void* const* d_in, const int* in_sizes, int n_in,
                              void* d_out, int out_size) {
    const float* lm  = (const float*)d_in[0];
    const float* lv  = (const float*)d_in[1];
    const float* Tin = (const float*)d_in[2];
    const float* cw0 = (const float*)d_in[3];
    const float* cb0 = (const float*)d_in[4];
    const float* cw1 = (const float*)d_in[5];
    const float* cb1 = (const float*)d_in[6];
    const float* cw2 = (const float*)d_in[7];
    const float* cb2 = (const float*)d_in[8];
    const float* pw0 = (const float*)d_in[9];
    const float* pb0 = (const float*)d_in[10];
    const float* pw1 = (const float*)d_in[11];
    const float* pb1 = (const float*)d_in[12];
    const float* pw2 = (const float*)d_in[13];
    const float* pb2 = (const float*)d_in[14];
    const float* fmw1 = (const float*)d_in[15];
    const float* fmb1 = (const float*)d_in[16];
    const float* fmw2 = (const float*)d_in[17];
    const float* fmb2 = (const float*)d_in[18];
    const float* fvw1 = (const float*)d_in[19];
    const float* fvb1 = (const float*)d_in[20];
    const float* fvw2 = (const float*)d_in[21];
    const float* fvb2 = (const float*)d_in[22];
    const float* lw0 = (const float*)d_in[23];
    const float* lb0 = (const float*)d_in[24];
    const float* lw1 = (const float*)d_in[25];
    const float* lb1 = (const float*)d_in[26];
    const float* lw2 = (const float*)d_in[27];
    const float* lb2 = (const float*)d_in[28];
    float* out = (float*)d_out;

    cudaFuncSetAttribute(mega_kernel, cudaFuncAttributeMaxDynamicSharedMemorySize,
                         MEGA_SMEM_BYTES);

    prep_kernel<<<1, 1024>>>(lw0, lw1, lw2, lb0, lb1, lb2, out);
    dim3 grid(GX, 4);
    mega_kernel<<<grid, BS, MEGA_SMEM_BYTES>>>(
        lm, lv, Tin,
        cw0, cb0, cw1, cb1, cw2, cb2,
        pw0, pb0, pw1, pb1, pw2, pb2,
        fmw1, fmb1, fmw2, fmb2,
        fvw1, fvb1, fvw2, fvb2,
        lb0, out);
}

// round 9
// speedup vs baseline: 1.8821x; 1.8821x over previous
#include <cuda_runtime.h>
#include <cstdint>

#define T_LEN 131072
#define D_X 16
#define D_L 8

// d_out layout (flat concat of reference tuple, all float32)
#define OFF_RECON 0
#define OFF_PRED  (T_LEN * D_X)
#define OFF_LMP   (2 * T_LEN * D_X)
#define OFF_LVP   (OFF_LMP + 2 * T_LEN * D_L)
#define OFF_CT    (OFF_LVP + 2 * T_LEN * D_L)
#define OFF_CT1   (OFF_CT + T_LEN * D_X * D_L)

typedef unsigned long long u64;

// ---------------------------------------------------------------------------
// Packed fp32x2 helpers (used by verified head path)
// ---------------------------------------------------------------------------
__device__ __forceinline__ u64 pk2(float x, float y) {
    u64 r;
    asm("mov.b64 %0, {%1, %2};" : "=l"(r) : "f"(x), "f"(y));
    return r;
}
__device__ __forceinline__ void upk2(u64 a, float& x, float& y) {
    asm("mov.b64 {%0, %1}, %2;" : "=f"(x), "=f"(y) : "l"(a));
}
__device__ __forceinline__ u64 ffma2u(u64 a, u64 b, u64 c) {
    u64 d;
    asm("fma.rn.f32x2 %0, %1, %2, %3;" : "=l"(d) : "l"(a), "l"(b), "l"(c));
    return d;
}

// tf32 conversion + mma
__device__ __forceinline__ float cvt_tf32(float x) {
    float r;
    asm("cvt.rna.tf32.f32 %0, %1;" : "=f"(r) : "f"(x));
    return r;
}
__device__ __forceinline__ void mma_tf32(float* c, const unsigned* a,
                                         const unsigned* b) {
    asm volatile(
        "mma.sync.aligned.m16n8k8.row.col.f32.tf32.tf32.f32 "
        "{%0,%1,%2,%3}, {%4,%5,%6,%7}, {%8,%9}, {%0,%1,%2,%3};"
        : "+f"(c[0]), "+f"(c[1]), "+f"(c[2]), "+f"(c[3])
        : "r"(a[0]), "r"(a[1]), "r"(a[2]), "r"(a[3]), "r"(b[0]), "r"(b[1]));
}

// ---------------------------------------------------------------------------
// Preprocessed decoder weights (device-global scratch; no allocation).
// ---------------------------------------------------------------------------
__device__ __align__(16) float g_w0t[D_X * 64 * 32];  // [n][j][f]
__device__ __align__(16) float g_w12[D_X * 64];       // collapsed lw1@lw2
__device__ __align__(16) float g_beff[D_X];           // lb1@lw2 + lb2

__global__ void prep_kernel(const float* __restrict__ lw0,
                            const float* __restrict__ lw1,
                            const float* __restrict__ lw2,
                            const float* __restrict__ lb0,
                            const float* __restrict__ lb1,
                            const float* __restrict__ lb2,
                            float* __restrict__ out) {
    int tid = threadIdx.x;          // 1024 threads: (n, j)
    int n = tid >> 6;
    int j = tid & 63;
#pragma unroll
    for (int f = 0; f < 32; f++)
        g_w0t[(n * 64 + j) * 32 + f] = lw0[(n * 32 + f) * 64 + j];
    float acc = 0.f;
#pragma unroll 8
    for (int o = 0; o < 64; o++)
        acc = fmaf(lw1[(n * 64 + j) * 64 + o], lw2[n * 64 + o], acc);
    g_w12[n * 64 + j] = acc;
    if (j == 0) {
        float b = lb2[n];
        for (int o = 0; o < 64; o++)
            b = fmaf(lb1[n * 64 + o], lw2[n * 64 + o], b);
        g_beff[n] = b;
    }
    __syncthreads();
    // pred[0]: features all-zero -> h = relu(lb0), out = relu(h.w12 + beff)
    if (j == 0) {
        float s = g_beff[n];
        for (int o = 0; o < 64; o++) {
            float h = fmaxf(lb0[n * 64 + o], 0.f);
            s = fmaf(h, g_w12[n * 64 + o], s);
        }
        out[OFF_PRED + n] = fmaxf(s, 0.f);
    }
}

// ---------------------------------------------------------------------------
// Encoder (verified round-2 code): packed smem block per branch.
// w0[8] b0[8] w1[64] b1[8] w2[1024] b2[128] = 1240 floats
// ---------------------------------------------------------------------------
#define EW0 0
#define EB0 8
#define EW1 16
#define EB1 80
#define EW2 88
#define EB2 1112
#define ESZ 1240

__device__ __forceinline__ void enc_branch(float s, const float* __restrict__ w,
                                           float* __restrict__ dst, bool binarize) {
    float h0[8], h1[8];
#pragma unroll
    for (int i = 0; i < 8; i++) {
        float v = fmaf(s, w[EW0 + i], w[EB0 + i]);
        h0[i] = v > 0.f ? v : 0.01f * v;
    }
#pragma unroll
    for (int j = 0; j < 8; j++) {
        float a = 0.f;
#pragma unroll
        for (int i = 0; i < 8; i++) a = fmaf(h0[i], w[EW1 + i * 8 + j], a);
        a += w[EB1 + j];
        h1[j] = a > 0.f ? a : 0.01f * a;
    }
#pragma unroll 4
    for (int m = 0; m < 128; m += 4) {
        float4 a = make_float4(0.f, 0.f, 0.f, 0.f);
#pragma unroll
        for (int j = 0; j < 8; j++) {
            float4 ww = *(const float4*)&w[EW2 + j * 128 + m];
            a.x = fmaf(h1[j], ww.x, a.x);
            a.y = fmaf(h1[j], ww.y, a.y);
            a.z = fmaf(h1[j], ww.z, a.z);
            a.w = fmaf(h1[j], ww.w, a.w);
        }
        a.x += w[EB2 + m + 0];
        a.y += w[EB2 + m + 1];
        a.z += w[EB2 + m + 2];
        a.w += w[EB2 + m + 3];
        if (binarize) {
            a.x = a.x < 0.1f ? 0.f : 1.f;
            a.y = a.y < 0.1f ? 0.f : 1.f;
            a.z = a.z < 0.1f ? 0.f : 1.f;
            a.w = a.w < 0.1f ? 0.f : 1.f;
        }
        *(float4*)&dst[m] = a;
    }
}

// ---------------------------------------------------------------------------
// Paired head (verified round-8 code).
// ---------------------------------------------------------------------------
__device__ __forceinline__ void head_fn2(const float* __restrict__ xa8,
                                         const float* __restrict__ xb8,
                                         const float* __restrict__ w1t,
                                         const float* __restrict__ b1,
                                         const float* __restrict__ w2,
                                         const float* __restrict__ b2,
                                         float* __restrict__ dsta,
                                         float* __restrict__ dstb) {
    const ulonglong2* xap = (const ulonglong2*)xa8;
    const ulonglong2* xbp = (const ulonglong2*)xb8;
    ulonglong2 xa01 = xap[0], xa23 = xap[1];
    ulonglong2 xb01 = xbp[0], xb23 = xbp[1];
    const ulonglong2* b2p = (const ulonglong2*)b2;
    ulonglong2 b2lo = b2p[0], b2hi = b2p[1];
    u64 oa0 = b2lo.x, oa1 = b2lo.y, oa2 = b2hi.x, oa3 = b2hi.y;
    u64 ob0 = oa0, ob1 = oa1, ob2 = oa2, ob3 = oa3;
    const ulonglong2* w1p = (const ulonglong2*)w1t;
    const ulonglong2* w2p = (const ulonglong2*)w2;
#pragma unroll 4
    for (int j = 0; j < 128; j++) {
        ulonglong2 wA = w1p[j * 2];
        ulonglong2 wB = w1p[j * 2 + 1];
        float bj = b1[j];
        u64 a0 = ffma2u(xa01.x, wA.x, 0ull);
        u64 a1 = ffma2u(xa23.x, wB.x, 0ull);
        a0 = ffma2u(xa01.y, wA.y, a0);
        a1 = ffma2u(xa23.y, wB.y, a1);
        u64 c0 = ffma2u(xb01.x, wA.x, 0ull);
        u64 c1 = ffma2u(xb23.x, wB.x, 0ull);
        c0 = ffma2u(xb01.y, wA.y, c0);
        c1 = ffma2u(xb23.y, wB.y, c1);
        float a0x, a0y, a1x, a1y, c0x, c0y, c1x, c1y;
        upk2(a0, a0x, a0y); upk2(a1, a1x, a1y);
        upk2(c0, c0x, c0y); upk2(c1, c1x, c1y);
        float ha = a0x + a0y + a1x + a1y + bj;
        float hb = c0x + c0y + c1x + c1y + bj;
        ha = fmaxf(ha, 0.f);
        hb = fmaxf(hb, 0.f);
        u64 hha = pk2(ha, ha);
        u64 hhb = pk2(hb, hb);
        ulonglong2 u = w2p[j * 2];
        ulonglong2 v = w2p[j * 2 + 1];
        oa0 = ffma2u(hha, u.x, oa0); oa1 = ffma2u(hha, u.y, oa1);
        oa2 = ffma2u(hha, v.x, oa2); oa3 = ffma2u(hha, v.y, oa3);
        ob0 = ffma2u(hhb, u.x, ob0); ob1 = ffma2u(hhb, u.y, ob1);
        ob2 = ffma2u(hhb, v.x, ob2); ob3 = ffma2u(hhb, v.y, ob3);
    }
    ulonglong2* da = (ulonglong2*)dsta;
    ulonglong2* db = (ulonglong2*)dstb;
    da[0] = make_ulonglong2(oa0, oa1);
    da[1] = make_ulonglong2(oa2, oa3);
    db[0] = make_ulonglong2(ob0, ob1);
    db[1] = make_ulonglong2(ob2, ob3);
}

// ---------------------------------------------------------------------------
// Kernel 2: enc (writes Ct, Ct1) + both heads, thread-per-t.
// ---------------------------------------------------------------------------
#define EH_B 256

// smem floats: s_c[1240] s_p[1240] mw1t[1024] mb1[128] mw2[1024] mb2[8]
//              vw1t[1024] vb1[128] vw2[1024] vb2[8]
#define E_C    0
#define E_P    (E_C + ESZ)
#define E_MW1T (E_P + ESZ)
#define E_MB1  (E_MW1T + 1024)
#define E_MW2  (E_MB1 + 128)
#define E_MB2  (E_MW2 + 1024)
#define E_VW1T (E_MB2 + 8)
#define E_VB1  (E_VW1T + 1024)
#define E_VW2  (E_VB1 + 128)
#define E_VB2  (E_VW2 + 1024)
#define E_TOT  (E_VB2 + 8)

__global__ __launch_bounds__(EH_B)
void encheads_kernel(const float* __restrict__ lm, const float* __restrict__ lv,
                     const float* __restrict__ Tin,
                     const float* cw0, const float* cb0, const float* cw1,
                     const float* cb1, const float* cw2, const float* cb2,
                     const float* pw0, const float* pb0, const float* pw1,
                     const float* pb1, const float* pw2, const float* pb2,
                     const float* fmw1, const float* fmb1,
                     const float* fmw2, const float* fmb2,
                     const float* fvw1, const float* fvb1,
                     const float* fvw2, const float* fvb2,
                     float* __restrict__ out) {
    __shared__ __align__(16) float smem[E_TOT];
    int tid = threadIdx.x;
    for (int i = tid; i < ESZ; i += EH_B) {
        float v, u;
        if (i < 8)         { v = cw0[i];        u = pw0[i];        }
        else if (i < 16)   { v = cb0[i - 8];    u = pb0[i - 8];    }
        else if (i < 80)   { v = cw1[i - 16];   u = pw1[i - 16];   }
        else if (i < 88)   { v = cb1[i - 80];   u = pb1[i - 80];   }
        else if (i < 1112) { v = cw2[i - 88];   u = pw2[i - 88];   }
        else               { v = cb2[i - 1112]; u = pb2[i - 1112]; }
        smem[E_C + i] = v;
        smem[E_P + i] = u;
    }
    for (int i = tid; i < 1024; i += EH_B) {
        int j = i >> 3, k = i & 7;
        smem[E_MW1T + i] = fmw1[k * 128 + j];   // transpose to [j][k]
        smem[E_VW1T + i] = fvw1[k * 128 + j];
        smem[E_MW2 + i]  = fmw2[i];
        smem[E_VW2 + i]  = fvw2[i];
    }
    if (tid < 128) { smem[E_MB1 + tid] = fmb1[tid]; smem[E_VB1 + tid] = fvb1[tid]; }
    if (tid < 8)   { smem[E_MB2 + tid] = fmb2[tid]; smem[E_VB2 + tid] = fvb2[tid]; }
    __syncthreads();

    size_t t = (size_t)blockIdx.x * EH_B + tid;
    float s = Tin[t];
    enc_branch(s, smem + E_C, out + OFF_CT + t * 128, true);
    enc_branch(s, smem + E_P, out + OFF_CT1 + t * 128, false);

    head_fn2(lm + t * 8, lm + ((size_t)T_LEN + t) * 8,
             smem + E_MW1T, smem + E_MB1, smem + E_MW2, smem + E_MB2,
             out + OFF_LMP + t * 8, out + OFF_LMP + ((size_t)T_LEN + t) * 8);
    head_fn2(lv + t * 8, lv + ((size_t)T_LEN + t) * 8,
             smem + E_VW1T, smem + E_VB1, smem + E_VW2, smem + E_VB2,
             out + OFF_LVP + t * 8, out + OFF_LVP + ((size_t)T_LEN + t) * 8);
}

// ---------------------------------------------------------------------------
// Kernel 3: tensor-core decode.
// CTA = 128-t tile; loops over 16 nodes. GEMM M=256 (128 recon rows + 128
// pred rows), N=64, K=32 per node via mma.m16n8k8.tf32.
// ---------------------------------------------------------------------------
#define DB 256
#define DGRID (T_LEN / 128)   // 1024

// smem float offsets
#define SD_LMV  0                 // [k8][c4][t128], c = mv*2+l : 4096
#define SD_A    4096              // 256 rows x 32, chunk-XOR swizzle : 8192
#define SD_W    12288             // 64 x 32 (tf32), chunk-XOR swizzle : 2048
#define SD_BW   14336             // [n][j] (b0, w12) pairs : 2048
#define SD_BEFF 16384             // 16
#define SD_TOT  16400
#define DEC_SMEM_BYTES (SD_TOT * 4)

// chunk-XOR swizzled float address within a stride-32 row
__device__ __forceinline__ int swz(int row, int col) {
    return row * 32 + ((((col) >> 2) ^ (row & 7)) << 2) + ((col) & 3);
}

__global__ __launch_bounds__(DB, 2)
void decode_kernel(const float* __restrict__ lm, const float* __restrict__ lv,
                   const float* __restrict__ lb0, float* __restrict__ out) {
    extern __shared__ __align__(16) float smem[];
    const int tid = threadIdx.x;
    const int warp = tid >> 5;
    const int lane = tid & 31;
    const int t0 = blockIdx.x * 128;

    // ---- load latent tile: [k][c][t] with c = mv*2 + l ----
    if (tid < 128) {
        int r = tid;
#pragma unroll
        for (int c = 0; c < 4; c++) {
            const float* base = (c & 2) ? lv : lm;
            const float4* row4 = (const float4*)base +
                ((size_t)((c & 1) ? T_LEN : 0) + t0 + r) * 2;
            float4 x0 = row4[0], x1 = row4[1];
            smem[SD_LMV + (0 * 4 + c) * 128 + r] = x0.x;
            smem[SD_LMV + (1 * 4 + c) * 128 + r] = x0.y;
            smem[SD_LMV + (2 * 4 + c) * 128 + r] = x0.z;
            smem[SD_LMV + (3 * 4 + c) * 128 + r] = x0.w;
            smem[SD_LMV + (4 * 4 + c) * 128 + r] = x1.x;
            smem[SD_LMV + (5 * 4 + c) * 128 + r] = x1.y;
            smem[SD_LMV + (6 * 4 + c) * 128 + r] = x1.z;
            smem[SD_LMV + (7 * 4 + c) * 128 + r] = x1.w;
        }
    }
    for (int i = tid; i < 1024; i += DB) {
        smem[SD_BW + 2 * i]     = lb0[i];
        smem[SD_BW + 2 * i + 1] = g_w12[i];
    }
    if (tid < 16) smem[SD_BEFF + tid] = g_beff[tid];
    __syncthreads();

    for (int n = 0; n < D_X; n++) {
        // ---- cooperative W_n load (convert to tf32, swizzled) ----
        for (int i = tid; i < 512; i += DB) {   // 512 float4 chunks
            int j = i >> 3, ch = i & 7;
            float4 w = ((const float4*)(g_w0t + n * 2048))[i];
            w.x = cvt_tf32(w.x); w.y = cvt_tf32(w.y);
            w.z = cvt_tf32(w.z); w.w = cvt_tf32(w.w);
            *(float4*)&smem[SD_W + j * 32 + ((ch ^ (j & 7)) << 2)] = w;
        }

        // ---- build staging A: row tid ----
        {
            int r = tid;
            float f[32];
            if (r < 128) {
                size_t t = (size_t)t0 + r;
                const float4* c4 = (const float4*)(out + OFF_CT + t * 128 + n * 8);
                float4 ca = c4[0], cb = c4[1];
                float ct[8] = {ca.x, ca.y, ca.z, ca.w, cb.x, cb.y, cb.z, cb.w};
#pragma unroll
                for (int k = 0; k < 8; k++) {
                    f[2 * k]      = ct[k] * smem[SD_LMV + (k * 4 + 0) * 128 + r];
                    f[2 * k + 1]  = ct[k] * smem[SD_LMV + (k * 4 + 1) * 128 + r];
                    f[16 + 2 * k]     = ct[k] * smem[SD_LMV + (k * 4 + 2) * 128 + r];
                    f[16 + 2 * k + 1] = ct[k] * smem[SD_LMV + (k * 4 + 3) * 128 + r];
                }
            } else {
                int rr = r - 128;
                size_t tt = (size_t)t0 + rr + 1;
                float cp[8];
                if (tt < T_LEN) {
                    const float4* c4 = (const float4*)(out + OFF_CT1 + tt * 128 + n * 8);
                    float4 ca = c4[0], cb = c4[1];
                    cp[0] = ca.x; cp[1] = ca.y; cp[2] = ca.z; cp[3] = ca.w;
                    cp[4] = cb.x; cp[5] = cb.y; cp[6] = cb.z; cp[7] = cb.w;
                } else {
#pragma unroll
                    for (int k = 0; k < 8; k++) cp[k] = 0.f;
                }
#pragma unroll
                for (int k = 0; k < 8; k++) {
                    f[2 * k]      = cp[k] * smem[SD_LMV + (k * 4 + 0) * 128 + rr];
                    f[2 * k + 1]  = cp[k] * smem[SD_LMV + (k * 4 + 1) * 128 + rr];
                    f[16 + 2 * k]     = cp[k] * smem[SD_LMV + (k * 4 + 2) * 128 + rr];
                    f[16 + 2 * k + 1] = cp[k] * smem[SD_LMV + (k * 4 + 3) * 128 + rr];
                }
            }
#pragma unroll
            for (int ch = 0; ch < 8; ch++) {
                float4 v = make_float4(cvt_tf32(f[ch * 4 + 0]), cvt_tf32(f[ch * 4 + 1]),
                                       cvt_tf32(f[ch * 4 + 2]), cvt_tf32(f[ch * 4 + 3]));
                *(float4*)&smem[SD_A + r * 32 + ((ch ^ (r & 7)) << 2)] = v;
            }
        }
        __syncthreads();

        // ---- mma: warp handles rows [warp*32, warp*32+32) ----
        const int m0w = warp * 32;
        float sums[2][2] = {{0.f, 0.f}, {0.f, 0.f}};   // [mtile][rowhalf]
        const float* SW = smem + SD_W;
        const float* SA = smem + SD_A;

        for (int nh = 0; nh < 2; nh++) {
            // B fragments for this N-half: 4 ntiles x 4 ktiles
            unsigned bfr[4][4][2];
#pragma unroll
            for (int nt = 0; nt < 4; nt++) {
                int j = nh * 32 + nt * 8 + (lane >> 2);
#pragma unroll
                for (int kt = 0; kt < 4; kt++) {
                    bfr[nt][kt][0] = __float_as_uint(
                        SW[j * 32 + (((kt * 2) ^ (j & 7)) << 2) + (lane & 3)]);
                    bfr[nt][kt][1] = __float_as_uint(
                        SW[j * 32 + (((kt * 2 + 1) ^ (j & 7)) << 2) + (lane & 3)]);
                }
            }
#pragma unroll
            for (int mt = 0; mt < 2; mt++) {
                int ra = m0w + mt * 16 + (lane >> 2);
                int rb = ra + 8;
                unsigned afr[4][4];
#pragma unroll
                for (int kt = 0; kt < 4; kt++) {
                    afr[kt][0] = __float_as_uint(
                        SA[ra * 32 + (((kt * 2) ^ (ra & 7)) << 2) + (lane & 3)]);
                    afr[kt][1] = __float_as_uint(
                        SA[rb * 32 + (((kt * 2) ^ (rb & 7)) << 2) + (lane & 3)]);
                    afr[kt][2] = __float_as_uint(
                        SA[ra * 32 + (((kt * 2 + 1) ^ (ra & 7)) << 2) + (lane & 3)]);
                    afr[kt][3] = __float_as_uint(
                        SA[rb * 32 + (((kt * 2 + 1) ^ (rb & 7)) << 2) + (lane & 3)]);
                }
#pragma unroll
                for (int nt = 0; nt < 4; nt++) {
                    float cfr[4] = {0.f, 0.f, 0.f, 0.f};
#pragma unroll
                    for (int kt = 0; kt < 4; kt++)
                        mma_tf32(cfr, afr[kt], bfr[nt][kt]);
                    // epilogue: h = relu(c + b0[j]); sum += h * w12[j]
                    int j0 = nh * 32 + nt * 8 + (lane & 3) * 2;
                    float4 bw2 = *(const float4*)&smem[SD_BW + (n * 64 + j0) * 2];
                    sums[mt][0] += fmaxf(cfr[0] + bw2.x, 0.f) * bw2.y +
                                   fmaxf(cfr[1] + bw2.z, 0.f) * bw2.w;
                    sums[mt][1] += fmaxf(cfr[2] + bw2.x, 0.f) * bw2.y +
                                   fmaxf(cfr[3] + bw2.z, 0.f) * bw2.w;
                }
            }
        }

        // ---- reduce over the 4 lanes sharing each row; store ----
        float be = smem[SD_BEFF + n];
#pragma unroll
        for (int mt = 0; mt < 2; mt++) {
#pragma unroll
            for (int h = 0; h < 2; h++) {
                float v = sums[mt][h];
                v += __shfl_xor_sync(0xffffffffu, v, 1);
                v += __shfl_xor_sync(0xffffffffu, v, 2);
                if ((lane & 3) == 0) {
                    int row = m0w + mt * 16 + h * 8 + (lane >> 2);
                    float val = fmaxf(v + be, 0.f);
                    if (row < 128) {
                        out[OFF_RECON + (size_t)(t0 + row) * 16 + n] = val;
                    } else {
                        size_t tt = (size_t)t0 + (row - 128) + 1;
                        if (tt < T_LEN)
                            out[OFF_PRED + tt * 16 + n] = val;
                    }
                }
            }
        }
        __syncthreads();   // staging/W reused next node
    }
}

// ---------------------------------------------------------------------------
extern "C" void kernel_launch(void* const* d_in, const int* in_sizes, int n_in,
                              void* d_out, int out_size) {
    const float* lm  = (const float*)d_in[0];
    const float* lv  = (const float*)d_in[1];
    const float* Tin = (const float*)d_in[2];
    const float* cw0 = (const float*)d_in[3];
    const float* cb0 = (const float*)d_in[4];
    const float* cw1 = (const float*)d_in[5];
    const float* cb1 = (const float*)d_in[6];
    const float* cw2 = (const float*)d_in[7];
    const float* cb2 = (const float*)d_in[8];
    const float* pw0 = (const float*)d_in[9];
    const float* pb0 = (const float*)d_in[10];
    const float* pw1 = (const float*)d_in[11];
    const float* pb1 = (const float*)d_in[12];
    const float* pw2 = (const float*)d_in[13];
    const float* pb2 = (const float*)d_in[14];
    const float* fmw1 = (const float*)d_in[15];
    const float* fmb1 = (const float*)d_in[16];
    const float* fmw2 = (const float*)d_in[17];
    const float* fmb2 = (const float*)d_in[18];
    const float* fvw1 = (const float*)d_in[19];
    const float* fvb1 = (const float*)d_in[20];
    const float* fvw2 = (const float*)d_in[21];
    const float* fvb2 = (const float*)d_in[22];
    const float* lw0 = (const float*)d_in[23];
    const float* lb0 = (const float*)d_in[24];
    const float* lw1 = (const float*)d_in[25];
    const float* lb1 = (const float*)d_in[26];
    const float* lw2 = (const float*)d_in[27];
    const float* lb2 = (const float*)d_in[28];
    float* out = (float*)d_out;

    cudaFuncSetAttribute(decode_kernel, cudaFuncAttributeMaxDynamicSharedMemorySize,
                         DEC_SMEM_BYTES);

    prep_kernel<<<1, 1024>>>(lw0, lw1, lw2, lb0, lb1, lb2, out);
    encheads_kernel<<<T_LEN / EH_B, EH_B>>>(
        lm, lv, Tin,
        cw0, cb0, cw1, cb1, cw2, cb2,
        pw0, pb0, pw1, pb1, pw2, pb2,
        fmw1, fmb1, fmw2, fmb2,
        fvw1, fvb1, fvw2, fvb2, out);
    decode_kernel<<<DGRID, DB, DEC_SMEM_BYTES>>>(lm, lv, lb0, out);
}

// round 10
// speedup vs baseline: 2.0129x; 1.0695x over previous
#include <cuda_runtime.h>
#include <cstdint>

#define T_LEN 131072
#define D_X 16
#define D_L 8

// d_out layout (flat concat of reference tuple, all float32)
#define OFF_RECON 0
#define OFF_PRED  (T_LEN * D_X)
#define OFF_LMP   (2 * T_LEN * D_X)
#define OFF_LVP   (OFF_LMP + 2 * T_LEN * D_L)
#define OFF_CT    (OFF_LVP + 2 * T_LEN * D_L)
#define OFF_CT1   (OFF_CT + T_LEN * D_X * D_L)

typedef unsigned long long u64;

// ---------------------------------------------------------------------------
// Packed fp32x2 helpers (verified head path)
// ---------------------------------------------------------------------------
__device__ __forceinline__ u64 pk2(float x, float y) {
    u64 r;
    asm("mov.b64 %0, {%1, %2};" : "=l"(r) : "f"(x), "f"(y));
    return r;
}
__device__ __forceinline__ void upk2(u64 a, float& x, float& y) {
    asm("mov.b64 {%0, %1}, %2;" : "=f"(x), "=f"(y) : "l"(a));
}
__device__ __forceinline__ u64 ffma2u(u64 a, u64 b, u64 c) {
    u64 d;
    asm("fma.rn.f32x2 %0, %1, %2, %3;" : "=l"(d) : "l"(a), "l"(b), "l"(c));
    return d;
}

// tf32 conversion + mma
__device__ __forceinline__ float cvt_tf32(float x) {
    float r;
    asm("cvt.rna.tf32.f32 %0, %1;" : "=f"(r) : "f"(x));
    return r;
}
__device__ __forceinline__ void mma_tf32(float* c, const unsigned* a,
                                         const unsigned* b) {
    asm volatile(
        "mma.sync.aligned.m16n8k8.row.col.f32.tf32.tf32.f32 "
        "{%0,%1,%2,%3}, {%4,%5,%6,%7}, {%8,%9}, {%0,%1,%2,%3};"
        : "+f"(c[0]), "+f"(c[1]), "+f"(c[2]), "+f"(c[3])
        : "r"(a[0]), "r"(a[1]), "r"(a[2]), "r"(a[3]), "r"(b[0]), "r"(b[1]));
}

// ---------------------------------------------------------------------------
// Preprocessed decoder weights (device-global scratch; no allocation).
// g_w0t now stores tf32-rounded values (decode uses them directly).
// ---------------------------------------------------------------------------
__device__ __align__(16) float g_w0t[D_X * 64 * 32];  // [n][j][f], tf32
__device__ __align__(16) float g_w12[D_X * 64];       // collapsed lw1@lw2
__device__ __align__(16) float g_beff[D_X];           // lb1@lw2 + lb2

// grid = 16 (one CTA per node), block = 64 (one thread per hidden j)
__global__ void prep_kernel(const float* __restrict__ lw0,
                            const float* __restrict__ lw1,
                            const float* __restrict__ lw2,
                            const float* __restrict__ lb0,
                            const float* __restrict__ lb1,
                            const float* __restrict__ lb2,
                            float* __restrict__ out) {
    int n = blockIdx.x;
    int j = threadIdx.x;
#pragma unroll
    for (int f = 0; f < 32; f++)
        g_w0t[(n * 64 + j) * 32 + f] = cvt_tf32(lw0[(n * 32 + f) * 64 + j]);
    float acc = 0.f;
#pragma unroll 8
    for (int o = 0; o < 64; o++)
        acc = fmaf(lw1[(n * 64 + j) * 64 + o], lw2[n * 64 + o], acc);
    g_w12[n * 64 + j] = acc;
    if (j == 0) {
        float b = lb2[n];
        for (int o = 0; o < 64; o++)
            b = fmaf(lb1[n * 64 + o], lw2[n * 64 + o], b);
        g_beff[n] = b;
    }
    __syncthreads();
    // pred[0]: features all-zero -> h = relu(lb0), out = relu(h.w12 + beff)
    if (j == 0) {
        float s = g_beff[n];
        for (int o = 0; o < 64; o++) {
            float h = fmaxf(lb0[n * 64 + o], 0.f);
            s = fmaf(h, g_w12[n * 64 + o], s);
        }
        out[OFF_PRED + n] = fmaxf(s, 0.f);
    }
}

// ---------------------------------------------------------------------------
// Encoder (verified round-2 code): packed smem block per branch.
// w0[8] b0[8] w1[64] b1[8] w2[1024] b2[128] = 1240 floats
// ---------------------------------------------------------------------------
#define EW0 0
#define EB0 8
#define EW1 16
#define EB1 80
#define EW2 88
#define EB2 1112
#define ESZ 1240

__device__ __forceinline__ void enc_branch(float s, const float* __restrict__ w,
                                           float* __restrict__ dst, bool binarize) {
    float h0[8], h1[8];
#pragma unroll
    for (int i = 0; i < 8; i++) {
        float v = fmaf(s, w[EW0 + i], w[EB0 + i]);
        h0[i] = v > 0.f ? v : 0.01f * v;
    }
#pragma unroll
    for (int j = 0; j < 8; j++) {
        float a = 0.f;
#pragma unroll
        for (int i = 0; i < 8; i++) a = fmaf(h0[i], w[EW1 + i * 8 + j], a);
        a += w[EB1 + j];
        h1[j] = a > 0.f ? a : 0.01f * a;
    }
#pragma unroll 4
    for (int m = 0; m < 128; m += 4) {
        float4 a = make_float4(0.f, 0.f, 0.f, 0.f);
#pragma unroll
        for (int j = 0; j < 8; j++) {
            float4 ww = *(const float4*)&w[EW2 + j * 128 + m];
            a.x = fmaf(h1[j], ww.x, a.x);
            a.y = fmaf(h1[j], ww.y, a.y);
            a.z = fmaf(h1[j], ww.z, a.z);
            a.w = fmaf(h1[j], ww.w, a.w);
        }
        a.x += w[EB2 + m + 0];
        a.y += w[EB2 + m + 1];
        a.z += w[EB2 + m + 2];
        a.w += w[EB2 + m + 3];
        if (binarize) {
            a.x = a.x < 0.1f ? 0.f : 1.f;
            a.y = a.y < 0.1f ? 0.f : 1.f;
            a.z = a.z < 0.1f ? 0.f : 1.f;
            a.w = a.w < 0.1f ? 0.f : 1.f;
        }
        *(float4*)&dst[m] = a;
    }
}

// ---------------------------------------------------------------------------
// Paired head (verified round-8 code).
// ---------------------------------------------------------------------------
__device__ __forceinline__ void head_fn2(const float* __restrict__ xa8,
                                         const float* __restrict__ xb8,
                                         const float* __restrict__ w1t,
                                         const float* __restrict__ b1,
                                         const float* __restrict__ w2,
                                         const float* __restrict__ b2,
                                         float* __restrict__ dsta,
                                         float* __restrict__ dstb) {
    const ulonglong2* xap = (const ulonglong2*)xa8;
    const ulonglong2* xbp = (const ulonglong2*)xb8;
    ulonglong2 xa01 = xap[0], xa23 = xap[1];
    ulonglong2 xb01 = xbp[0], xb23 = xbp[1];
    const ulonglong2* b2p = (const ulonglong2*)b2;
    ulonglong2 b2lo = b2p[0], b2hi = b2p[1];
    u64 oa0 = b2lo.x, oa1 = b2lo.y, oa2 = b2hi.x, oa3 = b2hi.y;
    u64 ob0 = oa0, ob1 = oa1, ob2 = oa2, ob3 = oa3;
    const ulonglong2* w1p = (const ulonglong2*)w1t;
    const ulonglong2* w2p = (const ulonglong2*)w2;
#pragma unroll 4
    for (int j = 0; j < 128; j++) {
        ulonglong2 wA = w1p[j * 2];
        ulonglong2 wB = w1p[j * 2 + 1];
        float bj = b1[j];
        u64 a0 = ffma2u(xa01.x, wA.x, 0ull);
        u64 a1 = ffma2u(xa23.x, wB.x, 0ull);
        a0 = ffma2u(xa01.y, wA.y, a0);
        a1 = ffma2u(xa23.y, wB.y, a1);
        u64 c0 = ffma2u(xb01.x, wA.x, 0ull);
        u64 c1 = ffma2u(xb23.x, wB.x, 0ull);
        c0 = ffma2u(xb01.y, wA.y, c0);
        c1 = ffma2u(xb23.y, wB.y, c1);
        float a0x, a0y, a1x, a1y, c0x, c0y, c1x, c1y;
        upk2(a0, a0x, a0y); upk2(a1, a1x, a1y);
        upk2(c0, c0x, c0y); upk2(c1, c1x, c1y);
        float ha = a0x + a0y + a1x + a1y + bj;
        float hb = c0x + c0y + c1x + c1y + bj;
        ha = fmaxf(ha, 0.f);
        hb = fmaxf(hb, 0.f);
        u64 hha = pk2(ha, ha);
        u64 hhb = pk2(hb, hb);
        ulonglong2 u = w2p[j * 2];
        ulonglong2 v = w2p[j * 2 + 1];
        oa0 = ffma2u(hha, u.x, oa0); oa1 = ffma2u(hha, u.y, oa1);
        oa2 = ffma2u(hha, v.x, oa2); oa3 = ffma2u(hha, v.y, oa3);
        ob0 = ffma2u(hhb, u.x, ob0); ob1 = ffma2u(hhb, u.y, ob1);
        ob2 = ffma2u(hhb, v.x, ob2); ob3 = ffma2u(hhb, v.y, ob3);
    }
    ulonglong2* da = (ulonglong2*)dsta;
    ulonglong2* db = (ulonglong2*)dstb;
    da[0] = make_ulonglong2(oa0, oa1);
    da[1] = make_ulonglong2(oa2, oa3);
    db[0] = make_ulonglong2(ob0, ob1);
    db[1] = make_ulonglong2(ob2, ob3);
}

// ---------------------------------------------------------------------------
// Kernel 2: enc (writes Ct, Ct1) + both heads, thread-per-t. (verified R9)
// ---------------------------------------------------------------------------
#define EH_B 256

#define E_C    0
#define E_P    (E_C + ESZ)
#define E_MW1T (E_P + ESZ)
#define E_MB1  (E_MW1T + 1024)
#define E_MW2  (E_MB1 + 128)
#define E_MB2  (E_MW2 + 1024)
#define E_VW1T (E_MB2 + 8)
#define E_VB1  (E_VW1T + 1024)
#define E_VW2  (E_VB1 + 128)
#define E_VB2  (E_VW2 + 1024)
#define E_TOT  (E_VB2 + 8)

__global__ __launch_bounds__(EH_B)
void encheads_kernel(const float* __restrict__ lm, const float* __restrict__ lv,
                     const float* __restrict__ Tin,
                     const float* cw0, const float* cb0, const float* cw1,
                     const float* cb1, const float* cw2, const float* cb2,
                     const float* pw0, const float* pb0, const float* pw1,
                     const float* pb1, const float* pw2, const float* pb2,
                     const float* fmw1, const float* fmb1,
                     const float* fmw2, const float* fmb2,
                     const float* fvw1, const float* fvb1,
                     const float* fvw2, const float* fvb2,
                     float* __restrict__ out) {
    __shared__ __align__(16) float smem[E_TOT];
    int tid = threadIdx.x;
    for (int i = tid; i < ESZ; i += EH_B) {
        float v, u;
        if (i < 8)         { v = cw0[i];        u = pw0[i];        }
        else if (i < 16)   { v = cb0[i - 8];    u = pb0[i - 8];    }
        else if (i < 80)   { v = cw1[i - 16];   u = pw1[i - 16];   }
        else if (i < 88)   { v = cb1[i - 80];   u = pb1[i - 80];   }
        else if (i < 1112) { v = cw2[i - 88];   u = pw2[i - 88];   }
        else               { v = cb2[i - 1112]; u = pb2[i - 1112]; }
        smem[E_C + i] = v;
        smem[E_P + i] = u;
    }
    for (int i = tid; i < 1024; i += EH_B) {
        int j = i >> 3, k = i & 7;
        smem[E_MW1T + i] = fmw1[k * 128 + j];
        smem[E_VW1T + i] = fvw1[k * 128 + j];
        smem[E_MW2 + i]  = fmw2[i];
        smem[E_VW2 + i]  = fvw2[i];
    }
    if (tid < 128) { smem[E_MB1 + tid] = fmb1[tid]; smem[E_VB1 + tid] = fvb1[tid]; }
    if (tid < 8)   { smem[E_MB2 + tid] = fmb2[tid]; smem[E_VB2 + tid] = fvb2[tid]; }
    __syncthreads();

    size_t t = (size_t)blockIdx.x * EH_B + tid;
    float s = Tin[t];
    enc_branch(s, smem + E_C, out + OFF_CT + t * 128, true);
    enc_branch(s, smem + E_P, out + OFF_CT1 + t * 128, false);

    head_fn2(lm + t * 8, lm + ((size_t)T_LEN + t) * 8,
             smem + E_MW1T, smem + E_MB1, smem + E_MW2, smem + E_MB2,
             out + OFF_LMP + t * 8, out + OFF_LMP + ((size_t)T_LEN + t) * 8);
    head_fn2(lv + t * 8, lv + ((size_t)T_LEN + t) * 8,
             smem + E_VW1T, smem + E_VB1, smem + E_VW2, smem + E_VB2,
             out + OFF_LVP + t * 8, out + OFF_LVP + ((size_t)T_LEN + t) * 8);
}

// ---------------------------------------------------------------------------
// Kernel 3: tensor-core decode (latents register-resident).
// CTA = 128-t tile; loops over 16 nodes. GEMM M=256 (128 recon + 128 pred),
// N=64, K=32 per node via mma.m16n8k8.tf32.
// ---------------------------------------------------------------------------
#define DB 256
#define DGRID (T_LEN / 128)   // 1024

// smem float offsets
#define SD_A    0                 // 256 rows x 32, chunk-XOR swizzle : 8192
#define SD_W    8192              // 64 x 32 (tf32), chunk-XOR swizzle : 2048
#define SD_BW   10240             // [n][j] (b0, w12) pairs : 2048
#define SD_BEFF 12288             // 16
#define SD_TOT  12304
#define DEC_SMEM_BYTES (SD_TOT * 4)

__global__ __launch_bounds__(DB, 2)
void decode_kernel(const float* __restrict__ lm, const float* __restrict__ lv,
                   const float* __restrict__ lb0, float* __restrict__ out) {
    extern __shared__ __align__(16) float smem[];
    const int tid = threadIdx.x;
    const int warp = tid >> 5;
    const int lane = tid & 31;
    const int t0 = blockIdx.x * 128;
    const bool isRecon = tid < 128;
    const int rr = isRecon ? tid : tid - 128;
    const size_t tl = (size_t)t0 + rr;

    // ---- latents register-resident: lat[2k+l] (M), lat[16+2k+l] (V).
    // Recon threads keep tf32-rounded copies (bit-identical to cvt(ct*M)
    // since ct is exactly 0/1); pred threads keep raw fp32 for cp-products.
    float lat[32];
    {
        const float4* lm4 = (const float4*)lm;
        const float4* lv4 = (const float4*)lv;
        float4 a0 = lm4[tl * 2], a1 = lm4[tl * 2 + 1];
        float4 b0 = lm4[((size_t)T_LEN + tl) * 2], b1 = lm4[((size_t)T_LEN + tl) * 2 + 1];
        float4 c0 = lv4[tl * 2], c1 = lv4[tl * 2 + 1];
        float4 d0 = lv4[((size_t)T_LEN + tl) * 2], d1 = lv4[((size_t)T_LEN + tl) * 2 + 1];
        const float* af = (const float*)&a0;   // a0,a1 contiguous? NO — keep explicit
        (void)af;
        float M0[8] = {a0.x, a0.y, a0.z, a0.w, a1.x, a1.y, a1.z, a1.w};
        float M1[8] = {b0.x, b0.y, b0.z, b0.w, b1.x, b1.y, b1.z, b1.w};
        float V0[8] = {c0.x, c0.y, c0.z, c0.w, c1.x, c1.y, c1.z, c1.w};
        float V1[8] = {d0.x, d0.y, d0.z, d0.w, d1.x, d1.y, d1.z, d1.w};
#pragma unroll
        for (int k = 0; k < 8; k++) {
            lat[2 * k]     = M0[k];
            lat[2 * k + 1] = M1[k];
            lat[16 + 2 * k]     = V0[k];
            lat[16 + 2 * k + 1] = V1[k];
        }
        if (isRecon) {
#pragma unroll
            for (int i = 0; i < 32; i++) lat[i] = cvt_tf32(lat[i]);
        }
    }

    for (int i = tid; i < 1024; i += DB) {
        smem[SD_BW + 2 * i]     = lb0[i];
        smem[SD_BW + 2 * i + 1] = g_w12[i];
    }
    if (tid < 16) smem[SD_BEFF + tid] = g_beff[tid];

    for (int n = 0; n < D_X; n++) {
        // ---- W_n copy (already tf32), swizzled ----
        for (int i = tid; i < 512; i += DB) {
            int j = i >> 3, ch = i & 7;
            float4 w = ((const float4*)(g_w0t + n * 2048))[i];
            *(float4*)&smem[SD_W + j * 32 + ((ch ^ (j & 7)) << 2)] = w;
        }

        // ---- staging A from registers ----
        {
            float f[32];
            if (isRecon) {
                const float4* c4 = (const float4*)(out + OFF_CT + tl * 128 + n * 8);
                float4 ca = c4[0], cb = c4[1];
                float ct[8] = {ca.x, ca.y, ca.z, ca.w, cb.x, cb.y, cb.z, cb.w};
#pragma unroll
                for (int k = 0; k < 8; k++) {
                    bool on = ct[k] > 0.5f;
                    f[2 * k]     = on ? lat[2 * k] : 0.f;
                    f[2 * k + 1] = on ? lat[2 * k + 1] : 0.f;
                    f[16 + 2 * k]     = on ? lat[16 + 2 * k] : 0.f;
                    f[16 + 2 * k + 1] = on ? lat[16 + 2 * k + 1] : 0.f;
                }
            } else {
                size_t tt = tl + 1;
                float cp[8];
                if (tt < T_LEN) {
                    const float4* c4 = (const float4*)(out + OFF_CT1 + tt * 128 + n * 8);
                    float4 ca = c4[0], cb = c4[1];
                    cp[0] = ca.x; cp[1] = ca.y; cp[2] = ca.z; cp[3] = ca.w;
                    cp[4] = cb.x; cp[5] = cb.y; cp[6] = cb.z; cp[7] = cb.w;
                } else {
#pragma unroll
                    for (int k = 0; k < 8; k++) cp[k] = 0.f;
                }
#pragma unroll
                for (int k = 0; k < 8; k++) {
                    f[2 * k]     = cvt_tf32(cp[k] * lat[2 * k]);
                    f[2 * k + 1] = cvt_tf32(cp[k] * lat[2 * k + 1]);
                    f[16 + 2 * k]     = cvt_tf32(cp[k] * lat[16 + 2 * k]);
                    f[16 + 2 * k + 1] = cvt_tf32(cp[k] * lat[16 + 2 * k + 1]);
                }
            }
#pragma unroll
            for (int ch = 0; ch < 8; ch++) {
                float4 v = make_float4(f[ch * 4 + 0], f[ch * 4 + 1],
                                       f[ch * 4 + 2], f[ch * 4 + 3]);
                *(float4*)&smem[SD_A + tid * 32 + ((ch ^ (tid & 7)) << 2)] = v;
            }
        }
        __syncthreads();

        // ---- mma: warp handles rows [warp*32, warp*32+32) ----
        const int m0w = warp * 32;
        float sums[2][2] = {{0.f, 0.f}, {0.f, 0.f}};
        const float* SW = smem + SD_W;
        const float* SA = smem + SD_A;

        for (int nh = 0; nh < 2; nh++) {
            unsigned bfr[4][4][2];
#pragma unroll
            for (int nt = 0; nt < 4; nt++) {
                int j = nh * 32 + nt * 8 + (lane >> 2);
#pragma unroll
                for (int kt = 0; kt < 4; kt++) {
                    bfr[nt][kt][0] = __float_as_uint(
                        SW[j * 32 + (((kt * 2) ^ (j & 7)) << 2) + (lane & 3)]);
                    bfr[nt][kt][1] = __float_as_uint(
                        SW[j * 32 + (((kt * 2 + 1) ^ (j & 7)) << 2) + (lane & 3)]);
                }
            }
#pragma unroll
            for (int mt = 0; mt < 2; mt++) {
                int ra = m0w + mt * 16 + (lane >> 2);
                int rb = ra + 8;
                unsigned afr[4][4];
#pragma unroll
                for (int kt = 0; kt < 4; kt++) {
                    afr[kt][0] = __float_as_uint(
                        SA[ra * 32 + (((kt * 2) ^ (ra & 7)) << 2) + (lane & 3)]);
                    afr[kt][1] = __float_as_uint(
                        SA[rb * 32 + (((kt * 2) ^ (rb & 7)) << 2) + (lane & 3)]);
                    afr[kt][2] = __float_as_uint(
                        SA[ra * 32 + (((kt * 2 + 1) ^ (ra & 7)) << 2) + (lane & 3)]);
                    afr[kt][3] = __float_as_uint(
                        SA[rb * 32 + (((kt * 2 + 1) ^ (rb & 7)) << 2) + (lane & 3)]);
                }
#pragma unroll
                for (int nt = 0; nt < 4; nt++) {
                    float cfr[4] = {0.f, 0.f, 0.f, 0.f};
#pragma unroll
                    for (int kt = 0; kt < 4; kt++)
                        mma_tf32(cfr, afr[kt], bfr[nt][kt]);
                    int j0 = nh * 32 + nt * 8 + (lane & 3) * 2;
                    float4 bw2 = *(const float4*)&smem[SD_BW + (n * 64 + j0) * 2];
                    sums[mt][0] += fmaxf(cfr[0] + bw2.x, 0.f) * bw2.y +
                                   fmaxf(cfr[1] + bw2.z, 0.f) * bw2.w;
                    sums[mt][1] += fmaxf(cfr[2] + bw2.x, 0.f) * bw2.y +
                                   fmaxf(cfr[3] + bw2.z, 0.f) * bw2.w;
                }
            }
        }

        // ---- reduce + store ----
        float be = smem[SD_BEFF + n];
#pragma unroll
        for (int mt = 0; mt < 2; mt++) {
#pragma unroll
            for (int h = 0; h < 2; h++) {
                float v = sums[mt][h];
                v += __shfl_xor_sync(0xffffffffu, v, 1);
                v += __shfl_xor_sync(0xffffffffu, v, 2);
                if ((lane & 3) == 0) {
                    int row = m0w + mt * 16 + h * 8 + (lane >> 2);
                    float val = fmaxf(v + be, 0.f);
                    if (row < 128) {
                        out[OFF_RECON + (size_t)(t0 + row) * 16 + n] = val;
                    } else {
                        size_t tt = (size_t)t0 + (row - 128) + 1;
                        if (tt < T_LEN)
                            out[OFF_PRED + tt * 16 + n] = val;
                    }
                }
            }
        }
        __syncthreads();
    }
}

// ---------------------------------------------------------------------------
extern "C" void kernel_launch(void* const* d_in, const int* in_sizes, int n_in,
                              void* d_out, int out_size) {
    const float* lm  = (const float*)d_in[0];
    const float* lv  = (const float*)d_in[1];
    const float* Tin = (const float*)d_in[2];
    const float* cw0 = (const float*)d_in[3];
    const float* cb0 = (const float*)d_in[4];
    const float* cw1 = (const float*)d_in[5];
    const float* cb1 = (const float*)d_in[6];
    const float* cw2 = (const float*)d_in[7];
    const float* cb2 = (const float*)d_in[8];
    const float* pw0 = (const float*)d_in[9];
    const float* pb0 = (const float*)d_in[10];
    const float* pw1 = (const float*)d_in[11];
    const float* pb1 = (const float*)d_in[12];
    const float* pw2 = (const float*)d_in[13];
    const float* pb2 = (const float*)d_in[14];
    const float* fmw1 = (const float*)d_in[15];
    const float* fmb1 = (const float*)d_in[16];
    const float* fmw2 = (const float*)d_in[17];
    const float* fmb2 = (const float*)d_in[18];
    const float* fvw1 = (const float*)d_in[19];
    const float* fvb1 = (const float*)d_in[20];
    const float* fvw2 = (const float*)d_in[21];
    const float* fvb2 = (const float*)d_in[22];
    const float* lw0 = (const float*)d_in[23];
    const float* lb0 = (const float*)d_in[24];
    const float* lw1 = (const float*)d_in[25];
    const float* lb1 = (const float*)d_in[26];
    const float* lw2 = (const float*)d_in[27];
    const float* lb2 = (const float*)d_in[28];
    float* out = (float*)d_out;

    cudaFuncSetAttribute(decode_kernel, cudaFuncAttributeMaxDynamicSharedMemorySize,
                         DEC_SMEM_BYTES);

    prep_kernel<<<16, 64>>>(lw0, lw1, lw2, lb0, lb1, lb2, out);
    encheads_kernel<<<T_LEN / EH_B, EH_B>>>(
        lm, lv, Tin,
        cw0, cb0, cw1, cb1, cw2, cb2,
        pw0, pb0, pw1, pb1, pw2, pb2,
        fmw1, fmb1, fmw2, fmb2,
        fvw1, fvb1, fvw2, fvb2, out);
    decode_kernel<<<DGRID, DB, DEC_SMEM_BYTES>>>(lm, lv, lb0, out);
}

// round 11
// speedup vs baseline: 2.1774x; 1.0817x over previous
#include <cuda_runtime.h>
#include <cstdint>

#define T_LEN 131072
#define D_X 16
#define D_L 8

// d_out layout (flat concat of reference tuple, all float32)
#define OFF_RECON 0
#define OFF_PRED  (T_LEN * D_X)
#define OFF_LMP   (2 * T_LEN * D_X)
#define OFF_LVP   (OFF_LMP + 2 * T_LEN * D_L)
#define OFF_CT    (OFF_LVP + 2 * T_LEN * D_L)
#define OFF_CT1   (OFF_CT + T_LEN * D_X * D_L)

typedef unsigned long long u64;

// ---------------------------------------------------------------------------
// Packed fp32x2 helpers (verified head path)
// ---------------------------------------------------------------------------
__device__ __forceinline__ u64 pk2(float x, float y) {
    u64 r;
    asm("mov.b64 %0, {%1, %2};" : "=l"(r) : "f"(x), "f"(y));
    return r;
}
__device__ __forceinline__ void upk2(u64 a, float& x, float& y) {
    asm("mov.b64 {%0, %1}, %2;" : "=f"(x), "=f"(y) : "l"(a));
}
__device__ __forceinline__ u64 ffma2u(u64 a, u64 b, u64 c) {
    u64 d;
    asm("fma.rn.f32x2 %0, %1, %2, %3;" : "=l"(d) : "l"(a), "l"(b), "l"(c));
    return d;
}

// tf32 conversion + mma
__device__ __forceinline__ float cvt_tf32(float x) {
    float r;
    asm("cvt.rna.tf32.f32 %0, %1;" : "=f"(r) : "f"(x));
    return r;
}
__device__ __forceinline__ void mma_tf32(float* c, const unsigned* a,
                                         const unsigned* b) {
    asm volatile(
        "mma.sync.aligned.m16n8k8.row.col.f32.tf32.tf32.f32 "
        "{%0,%1,%2,%3}, {%4,%5,%6,%7}, {%8,%9}, {%0,%1,%2,%3};"
        : "+f"(c[0]), "+f"(c[1]), "+f"(c[2]), "+f"(c[3])
        : "r"(a[0]), "r"(a[1]), "r"(a[2]), "r"(a[3]), "r"(b[0]), "r"(b[1]));
}

// ---------------------------------------------------------------------------
// Device-global scratch (no allocation).
// ---------------------------------------------------------------------------
__device__ __align__(16) float g_w0t[D_X * 64 * 32];  // [n][j][f], tf32
__device__ __align__(16) float g_w12[D_X * 64];       // collapsed lw1@lw2
__device__ __align__(16) float g_beff[D_X];           // lb1@lw2 + lb2
__device__ __align__(16) ulonglong2 g_mask[T_LEN];    // 128-bit Ct mask per t

// grid = 16 (one CTA per node), block = 256
__global__ void prep_kernel(const float* __restrict__ lw0,
                            const float* __restrict__ lw1,
                            const float* __restrict__ lw2,
                            const float* __restrict__ lb0,
                            const float* __restrict__ lb1,
                            const float* __restrict__ lb2,
                            float* __restrict__ out) {
    int n = blockIdx.x;
    int tid = threadIdx.x;
    int j = tid & 63;
    int q = tid >> 6;                  // 0..3, splits the transpose 4-way
#pragma unroll
    for (int ff = 0; ff < 8; ff++) {
        int f = q * 8 + ff;
        g_w0t[(n * 64 + j) * 32 + f] = cvt_tf32(lw0[(n * 32 + f) * 64 + j]);
    }
    if (q == 0) {
        float acc = 0.f;
#pragma unroll 8
        for (int o = 0; o < 64; o++)
            acc = fmaf(lw1[(n * 64 + j) * 64 + o], lw2[n * 64 + o], acc);
        g_w12[n * 64 + j] = acc;
        if (j == 0) {
            float b = lb2[n];
            for (int o = 0; o < 64; o++)
                b = fmaf(lb1[n * 64 + o], lw2[n * 64 + o], b);
            g_beff[n] = b;
        }
    }
    __syncthreads();
    // pred[0]: features all-zero -> h = relu(lb0), out = relu(h.w12 + beff)
    if (tid == 0) {
        float s = g_beff[n];
        for (int o = 0; o < 64; o++) {
            float h = fmaxf(lb0[n * 64 + o], 0.f);
            s = fmaf(h, g_w12[n * 64 + o], s);
        }
        out[OFF_PRED + n] = fmaxf(s, 0.f);
    }
}

// ---------------------------------------------------------------------------
// Encoder (verified round-2 arithmetic): packed smem block per branch.
// w0[8] b0[8] w1[64] b1[8] w2[1024] b2[128] = 1240 floats
// ---------------------------------------------------------------------------
#define EW0 0
#define EB0 8
#define EW1 16
#define EB1 80
#define EW2 88
#define EB2 1112
#define ESZ 1240

__device__ __forceinline__ void enc01h(float s, const float* __restrict__ w,
                                       float* __restrict__ h1) {
    float h0[8];
#pragma unroll
    for (int i = 0; i < 8; i++) {
        float v = fmaf(s, w[EW0 + i], w[EB0 + i]);
        h0[i] = v > 0.f ? v : 0.01f * v;
    }
#pragma unroll
    for (int j = 0; j < 8; j++) {
        float a = 0.f;
#pragma unroll
        for (int i = 0; i < 8; i++) a = fmaf(h0[i], w[EW1 + i * 8 + j], a);
        a += w[EB1 + j];
        h1[j] = a > 0.f ? a : 0.01f * a;
    }
}

// continuous branch (identical to verified enc_branch with binarize=false)
__device__ __forceinline__ void enc_branch_cont(float s, const float* __restrict__ w,
                                                float* __restrict__ dst) {
    float h1[8];
    enc01h(s, w, h1);
#pragma unroll 4
    for (int m = 0; m < 128; m += 4) {
        float4 a = make_float4(0.f, 0.f, 0.f, 0.f);
#pragma unroll
        for (int j = 0; j < 8; j++) {
            float4 ww = *(const float4*)&w[EW2 + j * 128 + m];
            a.x = fmaf(h1[j], ww.x, a.x);
            a.y = fmaf(h1[j], ww.y, a.y);
            a.z = fmaf(h1[j], ww.z, a.z);
            a.w = fmaf(h1[j], ww.w, a.w);
        }
        a.x += w[EB2 + m + 0];
        a.y += w[EB2 + m + 1];
        a.z += w[EB2 + m + 2];
        a.w += w[EB2 + m + 3];
        *(float4*)&dst[m] = a;
    }
}

// binarized branch: same arithmetic; also builds 128-bit mask (bit m set iff >= 0.1)
__device__ __forceinline__ void enc_branch_bin(float s, const float* __restrict__ w,
                                               float* __restrict__ dst,
                                               u64& mlo, u64& mhi) {
    float h1[8];
    enc01h(s, w, h1);
    mlo = 0ull; mhi = 0ull;
#pragma unroll 4
    for (int m = 0; m < 128; m += 4) {
        float4 a = make_float4(0.f, 0.f, 0.f, 0.f);
#pragma unroll
        for (int j = 0; j < 8; j++) {
            float4 ww = *(const float4*)&w[EW2 + j * 128 + m];
            a.x = fmaf(h1[j], ww.x, a.x);
            a.y = fmaf(h1[j], ww.y, a.y);
            a.z = fmaf(h1[j], ww.z, a.z);
            a.w = fmaf(h1[j], ww.w, a.w);
        }
        a.x += w[EB2 + m + 0];
        a.y += w[EB2 + m + 1];
        a.z += w[EB2 + m + 2];
        a.w += w[EB2 + m + 3];
        unsigned bits = 0;
        float4 o;
        if (a.x < 0.1f) { o.x = 0.f; } else { o.x = 1.f; bits |= 1u; }
        if (a.y < 0.1f) { o.y = 0.f; } else { o.y = 1.f; bits |= 2u; }
        if (a.z < 0.1f) { o.z = 0.f; } else { o.z = 1.f; bits |= 4u; }
        if (a.w < 0.1f) { o.w = 0.f; } else { o.w = 1.f; bits |= 8u; }
        if (m < 64) mlo |= (u64)bits << m;
        else        mhi |= (u64)bits << (m - 64);
        *(float4*)&dst[m] = o;
    }
}

// ---------------------------------------------------------------------------
// Paired head (verified round-8 code).
// ---------------------------------------------------------------------------
__device__ __forceinline__ void head_fn2(const float* __restrict__ xa8,
                                         const float* __restrict__ xb8,
                                         const float* __restrict__ w1t,
                                         const float* __restrict__ b1,
                                         const float* __restrict__ w2,
                                         const float* __restrict__ b2,
                                         float* __restrict__ dsta,
                                         float* __restrict__ dstb) {
    const ulonglong2* xap = (const ulonglong2*)xa8;
    const ulonglong2* xbp = (const ulonglong2*)xb8;
    ulonglong2 xa01 = xap[0], xa23 = xap[1];
    ulonglong2 xb01 = xbp[0], xb23 = xbp[1];
    const ulonglong2* b2p = (const ulonglong2*)b2;
    ulonglong2 b2lo = b2p[0], b2hi = b2p[1];
    u64 oa0 = b2lo.x, oa1 = b2lo.y, oa2 = b2hi.x, oa3 = b2hi.y;
    u64 ob0 = oa0, ob1 = oa1, ob2 = oa2, ob3 = oa3;
    const ulonglong2* w1p = (const ulonglong2*)w1t;
    const ulonglong2* w2p = (const ulonglong2*)w2;
#pragma unroll 4
    for (int j = 0; j < 128; j++) {
        ulonglong2 wA = w1p[j * 2];
        ulonglong2 wB = w1p[j * 2 + 1];
        float bj = b1[j];
        u64 a0 = ffma2u(xa01.x, wA.x, 0ull);
        u64 a1 = ffma2u(xa23.x, wB.x, 0ull);
        a0 = ffma2u(xa01.y, wA.y, a0);
        a1 = ffma2u(xa23.y, wB.y, a1);
        u64 c0 = ffma2u(xb01.x, wA.x, 0ull);
        u64 c1 = ffma2u(xb23.x, wB.x, 0ull);
        c0 = ffma2u(xb01.y, wA.y, c0);
        c1 = ffma2u(xb23.y, wB.y, c1);
        float a0x, a0y, a1x, a1y, c0x, c0y, c1x, c1y;
        upk2(a0, a0x, a0y); upk2(a1, a1x, a1y);
        upk2(c0, c0x, c0y); upk2(c1, c1x, c1y);
        float ha = a0x + a0y + a1x + a1y + bj;
        float hb = c0x + c0y + c1x + c1y + bj;
        ha = fmaxf(ha, 0.f);
        hb = fmaxf(hb, 0.f);
        u64 hha = pk2(ha, ha);
        u64 hhb = pk2(hb, hb);
        ulonglong2 u = w2p[j * 2];
        ulonglong2 v = w2p[j * 2 + 1];
        oa0 = ffma2u(hha, u.x, oa0); oa1 = ffma2u(hha, u.y, oa1);
        oa2 = ffma2u(hha, v.x, oa2); oa3 = ffma2u(hha, v.y, oa3);
        ob0 = ffma2u(hhb, u.x, ob0); ob1 = ffma2u(hhb, u.y, ob1);
        ob2 = ffma2u(hhb, v.x, ob2); ob3 = ffma2u(hhb, v.y, ob3);
    }
    ulonglong2* da = (ulonglong2*)dsta;
    ulonglong2* db = (ulonglong2*)dstb;
    da[0] = make_ulonglong2(oa0, oa1);
    da[1] = make_ulonglong2(oa2, oa3);
    db[0] = make_ulonglong2(ob0, ob1);
    db[1] = make_ulonglong2(ob2, ob3);
}

// ---------------------------------------------------------------------------
// Kernel 2: enc (writes Ct, Ct1, g_mask) + both heads, thread-per-t.
// ---------------------------------------------------------------------------
#define EH_B 256

#define E_C    0
#define E_P    (E_C + ESZ)
#define E_MW1T (E_P + ESZ)
#define E_MB1  (E_MW1T + 1024)
#define E_MW2  (E_MB1 + 128)
#define E_MB2  (E_MW2 + 1024)
#define E_VW1T (E_MB2 + 8)
#define E_VB1  (E_VW1T + 1024)
#define E_VW2  (E_VB1 + 128)
#define E_VB2  (E_VW2 + 1024)
#define E_TOT  (E_VB2 + 8)

__global__ __launch_bounds__(EH_B)
void encheads_kernel(const float* __restrict__ lm, const float* __restrict__ lv,
                     const float* __restrict__ Tin,
                     const float* cw0, const float* cb0, const float* cw1,
                     const float* cb1, const float* cw2, const float* cb2,
                     const float* pw0, const float* pb0, const float* pw1,
                     const float* pb1, const float* pw2, const float* pb2,
                     const float* fmw1, const float* fmb1,
                     const float* fmw2, const float* fmb2,
                     const float* fvw1, const float* fvb1,
                     const float* fvw2, const float* fvb2,
                     float* __restrict__ out) {
    __shared__ __align__(16) float smem[E_TOT];
    int tid = threadIdx.x;
    for (int i = tid; i < ESZ; i += EH_B) {
        float v, u;
        if (i < 8)         { v = cw0[i];        u = pw0[i];        }
        else if (i < 16)   { v = cb0[i - 8];    u = pb0[i - 8];    }
        else if (i < 80)   { v = cw1[i - 16];   u = pw1[i - 16];   }
        else if (i < 88)   { v = cb1[i - 80];   u = pb1[i - 80];   }
        else if (i < 1112) { v = cw2[i - 88];   u = pw2[i - 88];   }
        else               { v = cb2[i - 1112]; u = pb2[i - 1112]; }
        smem[E_C + i] = v;
        smem[E_P + i] = u;
    }
    for (int i = tid; i < 1024; i += EH_B) {
        int j = i >> 3, k = i & 7;
        smem[E_MW1T + i] = fmw1[k * 128 + j];
        smem[E_VW1T + i] = fvw1[k * 128 + j];
        smem[E_MW2 + i]  = fmw2[i];
        smem[E_VW2 + i]  = fvw2[i];
    }
    if (tid < 128) { smem[E_MB1 + tid] = fmb1[tid]; smem[E_VB1 + tid] = fvb1[tid]; }
    if (tid < 8)   { smem[E_MB2 + tid] = fmb2[tid]; smem[E_VB2 + tid] = fvb2[tid]; }
    __syncthreads();

    size_t t = (size_t)blockIdx.x * EH_B + tid;
    float s = Tin[t];
    u64 mlo, mhi;
    enc_branch_bin(s, smem + E_C, out + OFF_CT + t * 128, mlo, mhi);
    g_mask[t] = make_ulonglong2(mlo, mhi);
    enc_branch_cont(s, smem + E_P, out + OFF_CT1 + t * 128);

    head_fn2(lm + t * 8, lm + ((size_t)T_LEN + t) * 8,
             smem + E_MW1T, smem + E_MB1, smem + E_MW2, smem + E_MB2,
             out + OFF_LMP + t * 8, out + OFF_LMP + ((size_t)T_LEN + t) * 8);
    head_fn2(lv + t * 8, lv + ((size_t)T_LEN + t) * 8,
             smem + E_VW1T, smem + E_VB1, smem + E_VW2, smem + E_VB2,
             out + OFF_LVP + t * 8, out + OFF_LVP + ((size_t)T_LEN + t) * 8);
}

// ---------------------------------------------------------------------------
// Kernel 3: tensor-core decode. CTA = 128-t tile; loops over 16 nodes.
// GEMM M=256 (128 recon + 128 pred), N=64, K=32 per node (mma.m16n8k8.tf32).
// Recon gating comes from the g_mask bitmask (no Ct gmem reads).
// ---------------------------------------------------------------------------
#define DB 256
#define DGRID (T_LEN / 128)   // 1024

// smem float offsets
#define SD_A    0                 // 256 rows x 32, chunk-XOR swizzle : 8192
#define SD_W    8192              // 64 x 32 (tf32), chunk-XOR swizzle : 2048
#define SD_BW   10240             // [n][j] (b0, w12) pairs : 2048
#define SD_BEFF 12288             // 16
#define SD_TOT  12304
#define DEC_SMEM_BYTES (SD_TOT * 4)

__global__ __launch_bounds__(DB, 2)
void decode_kernel(const float* __restrict__ lm, const float* __restrict__ lv,
                   const float* __restrict__ lb0, float* __restrict__ out) {
    extern __shared__ __align__(16) float smem[];
    const int tid = threadIdx.x;
    const int warp = tid >> 5;
    const int lane = tid & 31;
    const int t0 = blockIdx.x * 128;
    const bool isRecon = tid < 128;
    const int rr = isRecon ? tid : tid - 128;
    const size_t tl = (size_t)t0 + rr;

    // latents register-resident, tf32-rounded on the recon side
    float lat[32];
    {
        const float4* lm4 = (const float4*)lm;
        const float4* lv4 = (const float4*)lv;
        float4 a0 = lm4[tl * 2], a1 = lm4[tl * 2 + 1];
        float4 b0 = lm4[((size_t)T_LEN + tl) * 2], b1 = lm4[((size_t)T_LEN + tl) * 2 + 1];
        float4 c0 = lv4[tl * 2], c1 = lv4[tl * 2 + 1];
        float4 d0 = lv4[((size_t)T_LEN + tl) * 2], d1 = lv4[((size_t)T_LEN + tl) * 2 + 1];
        float M0[8] = {a0.x, a0.y, a0.z, a0.w, a1.x, a1.y, a1.z, a1.w};
        float M1[8] = {b0.x, b0.y, b0.z, b0.w, b1.x, b1.y, b1.z, b1.w};
        float V0[8] = {c0.x, c0.y, c0.z, c0.w, c1.x, c1.y, c1.z, c1.w};
        float V1[8] = {d0.x, d0.y, d0.z, d0.w, d1.x, d1.y, d1.z, d1.w};
#pragma unroll
        for (int k = 0; k < 8; k++) {
            lat[2 * k]     = M0[k];
            lat[2 * k + 1] = M1[k];
            lat[16 + 2 * k]     = V0[k];
            lat[16 + 2 * k + 1] = V1[k];
        }
        if (isRecon) {
#pragma unroll
            for (int i = 0; i < 32; i++) lat[i] = cvt_tf32(lat[i]);
        }
    }
    // recon gating mask (one 16B load per thread for all 16 nodes)
    u64 mlo = 0ull, mhi = 0ull;
    if (isRecon) {
        ulonglong2 mk = g_mask[tl];
        mlo = mk.x; mhi = mk.y;
    }

    for (int i = tid; i < 1024; i += DB) {
        smem[SD_BW + 2 * i]     = lb0[i];
        smem[SD_BW + 2 * i + 1] = g_w12[i];
    }
    if (tid < 16) smem[SD_BEFF + tid] = g_beff[tid];

    for (int n = 0; n < D_X; n++) {
        // ---- W_n copy (already tf32), swizzled ----
        for (int i = tid; i < 512; i += DB) {
            int j = i >> 3, ch = i & 7;
            float4 w = ((const float4*)(g_w0t + n * 2048))[i];
            *(float4*)&smem[SD_W + j * 32 + ((ch ^ (j & 7)) << 2)] = w;
        }

        // ---- staging A from registers ----
        {
            float f[32];
            if (isRecon) {
                unsigned byte = (unsigned)((n < 8 ? (mlo >> (8 * n))
                                                  : (mhi >> (8 * (n - 8)))) & 0xffu);
#pragma unroll
                for (int k = 0; k < 8; k++) {
                    bool on = (byte >> k) & 1u;
                    f[2 * k]     = on ? lat[2 * k] : 0.f;
                    f[2 * k + 1] = on ? lat[2 * k + 1] : 0.f;
                    f[16 + 2 * k]     = on ? lat[16 + 2 * k] : 0.f;
                    f[16 + 2 * k + 1] = on ? lat[16 + 2 * k + 1] : 0.f;
                }
            } else {
                size_t tt = tl + 1;
                float cp[8];
                if (tt < T_LEN) {
                    const float4* c4 = (const float4*)(out + OFF_CT1 + tt * 128 + n * 8);
                    float4 ca = c4[0], cb = c4[1];
                    cp[0] = ca.x; cp[1] = ca.y; cp[2] = ca.z; cp[3] = ca.w;
                    cp[4] = cb.x; cp[5] = cb.y; cp[6] = cb.z; cp[7] = cb.w;
                } else {
#pragma unroll
                    for (int k = 0; k < 8; k++) cp[k] = 0.f;
                }
#pragma unroll
                for (int k = 0; k < 8; k++) {
                    f[2 * k]     = cvt_tf32(cp[k] * lat[2 * k]);
                    f[2 * k + 1] = cvt_tf32(cp[k] * lat[2 * k + 1]);
                    f[16 + 2 * k]     = cvt_tf32(cp[k] * lat[16 + 2 * k]);
                    f[16 + 2 * k + 1] = cvt_tf32(cp[k] * lat[16 + 2 * k + 1]);
                }
            }
#pragma unroll
            for (int ch = 0; ch < 8; ch++) {
                float4 v = make_float4(f[ch * 4 + 0], f[ch * 4 + 1],
                                       f[ch * 4 + 2], f[ch * 4 + 3]);
                *(float4*)&smem[SD_A + tid * 32 + ((ch ^ (tid & 7)) << 2)] = v;
            }
        }
        __syncthreads();

        // ---- mma: warp handles rows [warp*32, warp*32+32) ----
        const int m0w = warp * 32;
        float sums[2][2] = {{0.f, 0.f}, {0.f, 0.f}};
        const float* SW = smem + SD_W;
        const float* SA = smem + SD_A;

        // A fragments hoisted: loaded ONCE per node (independent of nh)
        unsigned afr[2][4][4];
#pragma unroll
        for (int mt = 0; mt < 2; mt++) {
            int ra = m0w + mt * 16 + (lane >> 2);
            int rb = ra + 8;
#pragma unroll
            for (int kt = 0; kt < 4; kt++) {
                afr[mt][kt][0] = __float_as_uint(
                    SA[ra * 32 + (((kt * 2) ^ (ra & 7)) << 2) + (lane & 3)]);
                afr[mt][kt][1] = __float_as_uint(
                    SA[rb * 32 + (((kt * 2) ^ (rb & 7)) << 2) + (lane & 3)]);
                afr[mt][kt][2] = __float_as_uint(
                    SA[ra * 32 + (((kt * 2 + 1) ^ (ra & 7)) << 2) + (lane & 3)]);
                afr[mt][kt][3] = __float_as_uint(
                    SA[rb * 32 + (((kt * 2 + 1) ^ (rb & 7)) << 2) + (lane & 3)]);
            }
        }

        for (int nh = 0; nh < 2; nh++) {
            unsigned bfr[4][4][2];
#pragma unroll
            for (int nt = 0; nt < 4; nt++) {
                int j = nh * 32 + nt * 8 + (lane >> 2);
#pragma unroll
                for (int kt = 0; kt < 4; kt++) {
                    bfr[nt][kt][0] = __float_as_uint(
                        SW[j * 32 + (((kt * 2) ^ (j & 7)) << 2) + (lane & 3)]);
                    bfr[nt][kt][1] = __float_as_uint(
                        SW[j * 32 + (((kt * 2 + 1) ^ (j & 7)) << 2) + (lane & 3)]);
                }
            }
#pragma unroll
            for (int mt = 0; mt < 2; mt++) {
#pragma unroll
                for (int nt = 0; nt < 4; nt++) {
                    float cfr[4] = {0.f, 0.f, 0.f, 0.f};
#pragma unroll
                    for (int kt = 0; kt < 4; kt++)
                        mma_tf32(cfr, afr[mt][kt], bfr[nt][kt]);
                    int j0 = nh * 32 + nt * 8 + (lane & 3) * 2;
                    float4 bw2 = *(const float4*)&smem[SD_BW + (n * 64 + j0) * 2];
                    sums[mt][0] += fmaxf(cfr[0] + bw2.x, 0.f) * bw2.y +
                                   fmaxf(cfr[1] + bw2.z, 0.f) * bw2.w;
                    sums[mt][1] += fmaxf(cfr[2] + bw2.x, 0.f) * bw2.y +
                                   fmaxf(cfr[3] + bw2.z, 0.f) * bw2.w;
                }
            }
        }

        // ---- reduce + store ----
        float be = smem[SD_BEFF + n];
#pragma unroll
        for (int mt = 0; mt < 2; mt++) {
#pragma unroll
            for (int h = 0; h < 2; h++) {
                float v = sums[mt][h];
                v += __shfl_xor_sync(0xffffffffu, v, 1);
                v += __shfl_xor_sync(0xffffffffu, v, 2);
                if ((lane & 3) == 0) {
                    int row = m0w + mt * 16 + h * 8 + (lane >> 2);
                    float val = fmaxf(v + be, 0.f);
                    if (row < 128) {
                        out[OFF_RECON + (size_t)(t0 + row) * 16 + n] = val;
                    } else {
                        size_t tt = (size_t)t0 + (row - 128) + 1;
                        if (tt < T_LEN)
                            out[OFF_PRED + tt * 16 + n] = val;
                    }
                }
            }
        }
        __syncthreads();
    }
}

// ---------------------------------------------------------------------------
extern "C" void kernel_launch(void* const* d_in, const int* in_sizes, int n_in,
                              void* d_out, int out_size) {
    const float* lm  = (const float*)d_in[0];
    const float* lv  = (const float*)d_in[1];
    const float* Tin = (const float*)d_in[2];
    const float* cw0 = (const float*)d_in[3];
    const float* cb0 = (const float*)d_in[4];
    const float* cw1 = (const float*)d_in[5];
    const float* cb1 = (const float*)d_in[6];
    const float* cw2 = (const float*)d_in[7];
    const float* cb2 = (const float*)d_in[8];
    const float* pw0 = (const float*)d_in[9];
    const float* pb0 = (const float*)d_in[10];
    const float* pw1 = (const float*)d_in[11];
    const float* pb1 = (const float*)d_in[12];
    const float* pw2 = (const float*)d_in[13];
    const float* pb2 = (const float*)d_in[14];
    const float* fmw1 = (const float*)d_in[15];
    const float* fmb1 = (const float*)d_in[16];
    const float* fmw2 = (const float*)d_in[17];
    const float* fmb2 = (const float*)d_in[18];
    const float* fvw1 = (const float*)d_in[19];
    const float* fvb1 = (const float*)d_in[20];
    const float* fvw2 = (const float*)d_in[21];
    const float* fvb2 = (const float*)d_in[22];
    const float* lw0 = (const float*)d_in[23];
    const float* lb0 = (const float*)d_in[24];
    const float* lw1 = (const float*)d_in[25];
    const float* lb1 = (const float*)d_in[26];
    const float* lw2 = (const float*)d_in[27];
    const float* lb2 = (const float*)d_in[28];
    float* out = (float*)d_out;

    cudaFuncSetAttribute(decode_kernel, cudaFuncAttributeMaxDynamicSharedMemorySize,
                         DEC_SMEM_BYTES);

    prep_kernel<<<16, 256>>>(lw0, lw1, lw2, lb0, lb1, lb2, out);
    encheads_kernel<<<T_LEN / EH_B, EH_B>>>(
        lm, lv, Tin,
        cw0, cb0, cw1, cb1, cw2, cb2,
        pw0, pb0, pw1, pb1, pw2, pb2,
        fmw1, fmb1, fmw2, fmb2,
        fvw1, fvb1, fvw2, fvb2, out);
    decode_kernel<<<DGRID, DB, DEC_SMEM_BYTES>>>(lm, lv, lb0, out);
}

// round 12
// speedup vs baseline: 2.4593x; 1.1295x over previous
#include <cuda_runtime.h>
#include <cstdint>

#define T_LEN 131072
#define D_X 16
#define D_L 8

// d_out layout (flat concat of reference tuple, all float32)
#define OFF_RECON 0
#define OFF_PRED  (T_LEN * D_X)
#define OFF_LMP   (2 * T_LEN * D_X)
#define OFF_LVP   (OFF_LMP + 2 * T_LEN * D_L)
#define OFF_CT    (OFF_LVP + 2 * T_LEN * D_L)
#define OFF_CT1   (OFF_CT + T_LEN * D_X * D_L)

typedef unsigned long long u64;

// ---------------------------------------------------------------------------
// Packed fp32x2 helpers (verified head path)
// ---------------------------------------------------------------------------
__device__ __forceinline__ u64 pk2(float x, float y) {
    u64 r;
    asm("mov.b64 %0, {%1, %2};" : "=l"(r) : "f"(x), "f"(y));
    return r;
}
__device__ __forceinline__ void upk2(u64 a, float& x, float& y) {
    asm("mov.b64 {%0, %1}, %2;" : "=f"(x), "=f"(y) : "l"(a));
}
__device__ __forceinline__ u64 ffma2u(u64 a, u64 b, u64 c) {
    u64 d;
    asm("fma.rn.f32x2 %0, %1, %2, %3;" : "=l"(d) : "l"(a), "l"(b), "l"(c));
    return d;
}

// tf32 conversion + mma
__device__ __forceinline__ float cvt_tf32(float x) {
    float r;
    asm("cvt.rna.tf32.f32 %0, %1;" : "=f"(r) : "f"(x));
    return r;
}
__device__ __forceinline__ void mma_tf32(float* c, const unsigned* a,
                                         const unsigned* b) {
    asm volatile(
        "mma.sync.aligned.m16n8k8.row.col.f32.tf32.tf32.f32 "
        "{%0,%1,%2,%3}, {%4,%5,%6,%7}, {%8,%9}, {%0,%1,%2,%3};"
        : "+f"(c[0]), "+f"(c[1]), "+f"(c[2]), "+f"(c[3])
        : "r"(a[0]), "r"(a[1]), "r"(a[2]), "r"(a[3]), "r"(b[0]), "r"(b[1]));
}

// ---------------------------------------------------------------------------
// Device-global scratch (no allocation).
// ---------------------------------------------------------------------------
__device__ __align__(16) float g_w0t[D_X * 64 * 32];  // [n][j][f], tf32
__device__ __align__(16) float g_w12[D_X * 64];       // collapsed lw1@lw2
__device__ __align__(16) float g_beff[D_X];           // lb1@lw2 + lb2

// grid = 16 (one CTA per node), block = 256
__global__ void prep_kernel(const float* __restrict__ lw0,
                            const float* __restrict__ lw1,
                            const float* __restrict__ lw2,
                            const float* __restrict__ lb0,
                            const float* __restrict__ lb1,
                            const float* __restrict__ lb2,
                            float* __restrict__ out) {
    int n = blockIdx.x;
    int tid = threadIdx.x;
    int j = tid & 63;
    int q = tid >> 6;
#pragma unroll
    for (int ff = 0; ff < 8; ff++) {
        int f = q * 8 + ff;
        g_w0t[(n * 64 + j) * 32 + f] = cvt_tf32(lw0[(n * 32 + f) * 64 + j]);
    }
    if (q == 0) {
        float acc = 0.f;
#pragma unroll 8
        for (int o = 0; o < 64; o++)
            acc = fmaf(lw1[(n * 64 + j) * 64 + o], lw2[n * 64 + o], acc);
        g_w12[n * 64 + j] = acc;
        if (j == 0) {
            float b = lb2[n];
            for (int o = 0; o < 64; o++)
                b = fmaf(lb1[n * 64 + o], lw2[n * 64 + o], b);
            g_beff[n] = b;
        }
    }
    __syncthreads();
    if (tid == 0) {
        float s = g_beff[n];
        for (int o = 0; o < 64; o++) {
            float h = fmaxf(lb0[n * 64 + o], 0.f);
            s = fmaf(h, g_w12[n * 64 + o], s);
        }
        out[OFF_PRED + n] = fmaxf(s, 0.f);
    }
}

// ---------------------------------------------------------------------------
// Encoder (verified round-2 arithmetic): packed smem block per branch.
// ---------------------------------------------------------------------------
#define EW0 0
#define EB0 8
#define EW1 16
#define EB1 80
#define EW2 88
#define EB2 1112
#define ESZ 1240

__device__ __forceinline__ void enc01h(float s, const float* __restrict__ w,
                                       float* __restrict__ h1) {
    float h0[8];
#pragma unroll
    for (int i = 0; i < 8; i++) {
        float v = fmaf(s, w[EW0 + i], w[EB0 + i]);
        h0[i] = v > 0.f ? v : 0.01f * v;
    }
#pragma unroll
    for (int j = 0; j < 8; j++) {
        float a = 0.f;
#pragma unroll
        for (int i = 0; i < 8; i++) a = fmaf(h0[i], w[EW1 + i * 8 + j], a);
        a += w[EB1 + j];
        h1[j] = a > 0.f ? a : 0.01f * a;
    }
}

__device__ __forceinline__ void enc_branch_cont(float s, const float* __restrict__ w,
                                                float* __restrict__ dst) {
    float h1[8];
    enc01h(s, w, h1);
#pragma unroll 4
    for (int m = 0; m < 128; m += 4) {
        float4 a = make_float4(0.f, 0.f, 0.f, 0.f);
#pragma unroll
        for (int j = 0; j < 8; j++) {
            float4 ww = *(const float4*)&w[EW2 + j * 128 + m];
            a.x = fmaf(h1[j], ww.x, a.x);
            a.y = fmaf(h1[j], ww.y, a.y);
            a.z = fmaf(h1[j], ww.z, a.z);
            a.w = fmaf(h1[j], ww.w, a.w);
        }
        a.x += w[EB2 + m + 0];
        a.y += w[EB2 + m + 1];
        a.z += w[EB2 + m + 2];
        a.w += w[EB2 + m + 3];
        *(float4*)&dst[m] = a;
    }
}

__device__ __forceinline__ void enc_branch_bin(float s, const float* __restrict__ w,
                                               float* __restrict__ dst,
                                               u64& mlo, u64& mhi) {
    float h1[8];
    enc01h(s, w, h1);
    mlo = 0ull; mhi = 0ull;
#pragma unroll 4
    for (int m = 0; m < 128; m += 4) {
        float4 a = make_float4(0.f, 0.f, 0.f, 0.f);
#pragma unroll
        for (int j = 0; j < 8; j++) {
            float4 ww = *(const float4*)&w[EW2 + j * 128 + m];
            a.x = fmaf(h1[j], ww.x, a.x);
            a.y = fmaf(h1[j], ww.y, a.y);
            a.z = fmaf(h1[j], ww.z, a.z);
            a.w = fmaf(h1[j], ww.w, a.w);
        }
        a.x += w[EB2 + m + 0];
        a.y += w[EB2 + m + 1];
        a.z += w[EB2 + m + 2];
        a.w += w[EB2 + m + 3];
        unsigned bits = 0;
        float4 o;
        if (a.x < 0.1f) { o.x = 0.f; } else { o.x = 1.f; bits |= 1u; }
        if (a.y < 0.1f) { o.y = 0.f; } else { o.y = 1.f; bits |= 2u; }
        if (a.z < 0.1f) { o.z = 0.f; } else { o.z = 1.f; bits |= 4u; }
        if (a.w < 0.1f) { o.w = 0.f; } else { o.w = 1.f; bits |= 8u; }
        if (m < 64) mlo |= (u64)bits << m;
        else        mhi |= (u64)bits << (m - 64);
        *(float4*)&dst[m] = o;
    }
}

// ---------------------------------------------------------------------------
// Paired head, x passed as packed register pairs (identical arithmetic to the
// verified head_fn2; xa01[0]=pk2(x0,x1), xa01[1]=pk2(x2,x3), etc.)
// ---------------------------------------------------------------------------
__device__ __forceinline__ void head_fn2r(const u64* __restrict__ xa,   // [4]
                                          const u64* __restrict__ xb,   // [4]
                                          const float* __restrict__ w1t,
                                          const float* __restrict__ b1,
                                          const float* __restrict__ w2,
                                          const float* __restrict__ b2,
                                          float* __restrict__ dsta,
                                          float* __restrict__ dstb) {
    const ulonglong2* b2p = (const ulonglong2*)b2;
    ulonglong2 b2lo = b2p[0], b2hi = b2p[1];
    u64 oa0 = b2lo.x, oa1 = b2lo.y, oa2 = b2hi.x, oa3 = b2hi.y;
    u64 ob0 = oa0, ob1 = oa1, ob2 = oa2, ob3 = oa3;
    const ulonglong2* w1p = (const ulonglong2*)w1t;
    const ulonglong2* w2p = (const ulonglong2*)w2;
#pragma unroll 4
    for (int j = 0; j < 128; j++) {
        ulonglong2 wA = w1p[j * 2];
        ulonglong2 wB = w1p[j * 2 + 1];
        float bj = b1[j];
        u64 a0 = ffma2u(xa[0], wA.x, 0ull);
        u64 a1 = ffma2u(xa[2], wB.x, 0ull);
        a0 = ffma2u(xa[1], wA.y, a0);
        a1 = ffma2u(xa[3], wB.y, a1);
        u64 c0 = ffma2u(xb[0], wA.x, 0ull);
        u64 c1 = ffma2u(xb[2], wB.x, 0ull);
        c0 = ffma2u(xb[1], wA.y, c0);
        c1 = ffma2u(xb[3], wB.y, c1);
        float a0x, a0y, a1x, a1y, c0x, c0y, c1x, c1y;
        upk2(a0, a0x, a0y); upk2(a1, a1x, a1y);
        upk2(c0, c0x, c0y); upk2(c1, c1x, c1y);
        float ha = a0x + a0y + a1x + a1y + bj;
        float hb = c0x + c0y + c1x + c1y + bj;
        ha = fmaxf(ha, 0.f);
        hb = fmaxf(hb, 0.f);
        u64 hha = pk2(ha, ha);
        u64 hhb = pk2(hb, hb);
        ulonglong2 u = w2p[j * 2];
        ulonglong2 v = w2p[j * 2 + 1];
        oa0 = ffma2u(hha, u.x, oa0); oa1 = ffma2u(hha, u.y, oa1);
        oa2 = ffma2u(hha, v.x, oa2); oa3 = ffma2u(hha, v.y, oa3);
        ob0 = ffma2u(hhb, u.x, ob0); ob1 = ffma2u(hhb, u.y, ob1);
        ob2 = ffma2u(hhb, v.x, ob2); ob3 = ffma2u(hhb, v.y, ob3);
    }
    ulonglong2* da = (ulonglong2*)dsta;
    ulonglong2* db = (ulonglong2*)dstb;
    da[0] = make_ulonglong2(oa0, oa1);
    da[1] = make_ulonglong2(oa2, oa3);
    db[0] = make_ulonglong2(ob0, ob1);
    db[1] = make_ulonglong2(ob2, ob3);
}

// ---------------------------------------------------------------------------
// Fused kernel: enc + heads + tensor-core decode. CTA = 128-t tile.
// tid<128: recon thread for t=t0+tid (enc-C + mask + lm heads + recon rows)
// tid>=128: pred thread, rr=tid-128 (enc-P at t+1 + lv heads + pred rows)
// ---------------------------------------------------------------------------
#define DB 256
#define DGRID (T_LEN / 128)   // 1024

// smem float offsets
#define SD_A    0                 // 256 x 32, chunk-XOR swizzle : 8192
#define SD_W    8192              // 64 x 32 (tf32), swizzle : 2048
#define SD_BW   10240             // [n][j] (b0, w12) pairs : 2048
#define SD_BEFF 12288             // 16
#define E_C     12304             // 1240
#define E_P     (E_C + ESZ)       // 13544
#define E_MW1T  (E_P + ESZ)       // 14784
#define E_MB1   (E_MW1T + 1024)   // 15808
#define E_MW2   (E_MB1 + 128)     // 15936
#define E_MB2   (E_MW2 + 1024)    // 16960
#define E_VW1T  (E_MB2 + 8)       // 16968
#define E_VB1   (E_VW1T + 1024)   // 17992
#define E_VW2   (E_VB1 + 128)     // 18120
#define E_VB2   (E_VW2 + 1024)    // 19144
#define SD_TOT  (E_VB2 + 8)       // 19152
#define FUSED_SMEM_BYTES (SD_TOT * 4)   // 76608 B -> 2 CTA/SM

__global__ __launch_bounds__(DB, 2)
void fused_kernel(const float* __restrict__ lm, const float* __restrict__ lv,
                  const float* __restrict__ Tin,
                  const float* cw0, const float* cb0, const float* cw1,
                  const float* cb1, const float* cw2, const float* cb2,
                  const float* pw0, const float* pb0, const float* pw1,
                  const float* pb1, const float* pw2, const float* pb2,
                  const float* fmw1, const float* fmb1,
                  const float* fmw2, const float* fmb2,
                  const float* fvw1, const float* fvb1,
                  const float* fvw2, const float* fvb2,
                  const float* __restrict__ lb0, float* __restrict__ out) {
    extern __shared__ __align__(16) float smem[];
    const int tid = threadIdx.x;
    const int warp = tid >> 5;
    const int lane = tid & 31;
    const int t0 = blockIdx.x * 128;
    const bool isRecon = tid < 128;
    const int rr = isRecon ? tid : tid - 128;
    const size_t tl = (size_t)t0 + rr;

    // ---- cooperative smem fill ----
    for (int i = tid; i < ESZ; i += DB) {
        float v, u;
        if (i < 8)         { v = cw0[i];        u = pw0[i];        }
        else if (i < 16)   { v = cb0[i - 8];    u = pb0[i - 8];    }
        else if (i < 80)   { v = cw1[i - 16];   u = pw1[i - 16];   }
        else if (i < 88)   { v = cb1[i - 80];   u = pb1[i - 80];   }
        else if (i < 1112) { v = cw2[i - 88];   u = pw2[i - 88];   }
        else               { v = cb2[i - 1112]; u = pb2[i - 1112]; }
        smem[E_C + i] = v;
        smem[E_P + i] = u;
    }
    for (int i = tid; i < 1024; i += DB) {
        int j = i >> 3, k = i & 7;
        smem[E_MW1T + i] = fmw1[k * 128 + j];
        smem[E_VW1T + i] = fvw1[k * 128 + j];
        smem[E_MW2 + i]  = fmw2[i];
        smem[E_VW2 + i]  = fvw2[i];
        smem[SD_BW + 2 * i]     = lb0[i];
        smem[SD_BW + 2 * i + 1] = g_w12[i];
    }
    if (tid < 128) { smem[E_MB1 + tid] = fmb1[tid]; smem[E_VB1 + tid] = fvb1[tid]; }
    if (tid < 8)   { smem[E_MB2 + tid] = fmb2[tid]; smem[E_VB2 + tid] = fvb2[tid]; }
    if (tid < 16)  smem[SD_BEFF + tid] = g_beff[tid];
    __syncthreads();

    // ---- latents register-resident (raw fp32 for enc/head phase) ----
    float lat[32];
    {
        const float4* lm4 = (const float4*)lm;
        const float4* lv4 = (const float4*)lv;
        float4 a0 = lm4[tl * 2], a1 = lm4[tl * 2 + 1];
        float4 b0 = lm4[((size_t)T_LEN + tl) * 2], b1 = lm4[((size_t)T_LEN + tl) * 2 + 1];
        float4 c0 = lv4[tl * 2], c1 = lv4[tl * 2 + 1];
        float4 d0 = lv4[((size_t)T_LEN + tl) * 2], d1 = lv4[((size_t)T_LEN + tl) * 2 + 1];
        float M0[8] = {a0.x, a0.y, a0.z, a0.w, a1.x, a1.y, a1.z, a1.w};
        float M1[8] = {b0.x, b0.y, b0.z, b0.w, b1.x, b1.y, b1.z, b1.w};
        float V0[8] = {c0.x, c0.y, c0.z, c0.w, c1.x, c1.y, c1.z, c1.w};
        float V1[8] = {d0.x, d0.y, d0.z, d0.w, d1.x, d1.y, d1.z, d1.w};
#pragma unroll
        for (int k = 0; k < 8; k++) {
            lat[2 * k]     = M0[k];
            lat[2 * k + 1] = M1[k];
            lat[16 + 2 * k]     = V0[k];
            lat[16 + 2 * k + 1] = V1[k];
        }
    }

    // ---- enc phase ----
    u64 mlo = 0ull, mhi = 0ull;
    if (isRecon) {
        float s = Tin[tl];
        enc_branch_bin(s, smem + E_C, out + OFF_CT + tl * 128, mlo, mhi);
        if (t0 == 0 && tid == 0)
            enc_branch_cont(Tin[0], smem + E_P, out + OFF_CT1);
    } else {
        size_t tt = tl + 1;
        if (tt < T_LEN)
            enc_branch_cont(Tin[tt], smem + E_P, out + OFF_CT1 + tt * 128);
    }

    // ---- head phase: recon thread -> lm heads; pred thread -> lv heads ----
    {
        u64 xa[4], xb[4];
        int base = isRecon ? 0 : 16;
#pragma unroll
        for (int i = 0; i < 4; i++) {
            xa[i] = pk2(lat[base + 4 * i], lat[base + 4 * i + 2]);
            xb[i] = pk2(lat[base + 4 * i + 1], lat[base + 4 * i + 3]);
        }
        const float* w1t = isRecon ? smem + E_MW1T : smem + E_VW1T;
        const float* b1h = isRecon ? smem + E_MB1  : smem + E_VB1;
        const float* w2h = isRecon ? smem + E_MW2  : smem + E_VW2;
        const float* b2h = isRecon ? smem + E_MB2  : smem + E_VB2;
        float* hdst = out + (isRecon ? OFF_LMP : OFF_LVP);
        head_fn2r(xa, xb, w1t, b1h, w2h, b2h,
                  hdst + tl * 8, hdst + ((size_t)T_LEN + tl) * 8);
    }

    // recon lat -> tf32
    if (isRecon) {
#pragma unroll
        for (int i = 0; i < 32; i++) lat[i] = cvt_tf32(lat[i]);
    }

    // ---- decode node loop (verified R11 structure) ----
    for (int n = 0; n < D_X; n++) {
        for (int i = tid; i < 512; i += DB) {
            int j = i >> 3, ch = i & 7;
            float4 w = ((const float4*)(g_w0t + n * 2048))[i];
            *(float4*)&smem[SD_W + j * 32 + ((ch ^ (j & 7)) << 2)] = w;
        }
        {
            float f[32];
            if (isRecon) {
                unsigned byte = (unsigned)((n < 8 ? (mlo >> (8 * n))
                                                  : (mhi >> (8 * (n - 8)))) & 0xffu);
#pragma unroll
                for (int k = 0; k < 8; k++) {
                    bool on = (byte >> k) & 1u;
                    f[2 * k]     = on ? lat[2 * k] : 0.f;
                    f[2 * k + 1] = on ? lat[2 * k + 1] : 0.f;
                    f[16 + 2 * k]     = on ? lat[16 + 2 * k] : 0.f;
                    f[16 + 2 * k + 1] = on ? lat[16 + 2 * k + 1] : 0.f;
                }
            } else {
                size_t tt = tl + 1;
                float cp[8];
                if (tt < T_LEN) {
                    const float4* c4 = (const float4*)(out + OFF_CT1 + tt * 128 + n * 8);
                    float4 ca = c4[0], cb = c4[1];
                    cp[0] = ca.x; cp[1] = ca.y; cp[2] = ca.z; cp[3] = ca.w;
                    cp[4] = cb.x; cp[5] = cb.y; cp[6] = cb.z; cp[7] = cb.w;
                } else {
#pragma unroll
                    for (int k = 0; k < 8; k++) cp[k] = 0.f;
                }
#pragma unroll
                for (int k = 0; k < 8; k++) {
                    f[2 * k]     = cvt_tf32(cp[k] * lat[2 * k]);
                    f[2 * k + 1] = cvt_tf32(cp[k] * lat[2 * k + 1]);
                    f[16 + 2 * k]     = cvt_tf32(cp[k] * lat[16 + 2 * k]);
                    f[16 + 2 * k + 1] = cvt_tf32(cp[k] * lat[16 + 2 * k + 1]);
                }
            }
#pragma unroll
            for (int ch = 0; ch < 8; ch++) {
                float4 v = make_float4(f[ch * 4 + 0], f[ch * 4 + 1],
                                       f[ch * 4 + 2], f[ch * 4 + 3]);
                *(float4*)&smem[SD_A + tid * 32 + ((ch ^ (tid & 7)) << 2)] = v;
            }
        }
        __syncthreads();

        const int m0w = warp * 32;
        float sums[2][2] = {{0.f, 0.f}, {0.f, 0.f}};
        const float* SW = smem + SD_W;
        const float* SA = smem + SD_A;

        unsigned afr[2][4][4];
#pragma unroll
        for (int mt = 0; mt < 2; mt++) {
            int ra = m0w + mt * 16 + (lane >> 2);
            int rb = ra + 8;
#pragma unroll
            for (int kt = 0; kt < 4; kt++) {
                afr[mt][kt][0] = __float_as_uint(
                    SA[ra * 32 + (((kt * 2) ^ (ra & 7)) << 2) + (lane & 3)]);
                afr[mt][kt][1] = __float_as_uint(
                    SA[rb * 32 + (((kt * 2) ^ (rb & 7)) << 2) + (lane & 3)]);
                afr[mt][kt][2] = __float_as_uint(
                    SA[ra * 32 + (((kt * 2 + 1) ^ (ra & 7)) << 2) + (lane & 3)]);
                afr[mt][kt][3] = __float_as_uint(
                    SA[rb * 32 + (((kt * 2 + 1) ^ (rb & 7)) << 2) + (lane & 3)]);
            }
        }

        for (int nh = 0; nh < 2; nh++) {
            unsigned bfr[4][4][2];
#pragma unroll
            for (int nt = 0; nt < 4; nt++) {
                int j = nh * 32 + nt * 8 + (lane >> 2);
#pragma unroll
                for (int kt = 0; kt < 4; kt++) {
                    bfr[nt][kt][0] = __float_as_uint(
                        SW[j * 32 + (((kt * 2) ^ (j & 7)) << 2) + (lane & 3)]);
                    bfr[nt][kt][1] = __float_as_uint(
                        SW[j * 32 + (((kt * 2 + 1) ^ (j & 7)) << 2) + (lane & 3)]);
                }
            }
#pragma unroll
            for (int mt = 0; mt < 2; mt++) {
#pragma unroll
                for (int nt = 0; nt < 4; nt++) {
                    float cfr[4] = {0.f, 0.f, 0.f, 0.f};
#pragma unroll
                    for (int kt = 0; kt < 4; kt++)
                        mma_tf32(cfr, afr[mt][kt], bfr[nt][kt]);
                    int j0 = nh * 32 + nt * 8 + (lane & 3) * 2;
                    float4 bw2 = *(const float4*)&smem[SD_BW + (n * 64 + j0) * 2];
                    sums[mt][0] += fmaxf(cfr[0] + bw2.x, 0.f) * bw2.y +
                                   fmaxf(cfr[1] + bw2.z, 0.f) * bw2.w;
                    sums[mt][1] += fmaxf(cfr[2] + bw2.x, 0.f) * bw2.y +
                                   fmaxf(cfr[3] + bw2.z, 0.f) * bw2.w;
                }
            }
        }

        float be = smem[SD_BEFF + n];
#pragma unroll
        for (int mt = 0; mt < 2; mt++) {
#pragma unroll
            for (int h = 0; h < 2; h++) {
                float v = sums[mt][h];
                v += __shfl_xor_sync(0xffffffffu, v, 1);
                v += __shfl_xor_sync(0xffffffffu, v, 2);
                if ((lane & 3) == 0) {
                    int row = m0w + mt * 16 + h * 8 + (lane >> 2);
                    float val = fmaxf(v + be, 0.f);
                    if (row < 128) {
                        out[OFF_RECON + (size_t)(t0 + row) * 16 + n] = val;
                    } else {
                        size_t tt = (size_t)t0 + (row - 128) + 1;
                        if (tt < T_LEN)
                            out[OFF_PRED + tt * 16 + n] = val;
                    }
                }
            }
        }
        __syncthreads();
    }
}

// ---------------------------------------------------------------------------
extern "C" void kernel_launch(void* const* d_in, const int* in_sizes, int n_in,
                              void* d_out, int out_size) {
    const float* lm  = (const float*)d_in[0];
    const float* lv  = (const float*)d_in[1];
    const float* Tin = (const float*)d_in[2];
    const float* cw0 = (const float*)d_in[3];
    const float* cb0 = (const float*)d_in[4];
    const float* cw1 = (const float*)d_in[5];
    const float* cb1 = (const float*)d_in[6];
    const float* cw2 = (const float*)d_in[7];
    const float* cb2 = (const float*)d_in[8];
    const float* pw0 = (const float*)d_in[9];
    const float* pb0 = (const float*)d_in[10];
    const float* pw1 = (const float*)d_in[11];
    const float* pb1 = (const float*)d_in[12];
    const float* pw2 = (const float*)d_in[13];
    const float* pb2 = (const float*)d_in[14];
    const float* fmw1 = (const float*)d_in[15];
    const float* fmb1 = (const float*)d_in[16];
    const float* fmw2 = (const float*)d_in[17];
    const float* fmb2 = (const float*)d_in[18];
    const float* fvw1 = (const float*)d_in[19];
    const float* fvb1 = (const float*)d_in[20];
    const float* fvw2 = (const float*)d_in[21];
    const float* fvb2 = (const float*)d_in[22];
    const float* lw0 = (const float*)d_in[23];
    const float* lb0 = (const float*)d_in[24];
    const float* lw1 = (const float*)d_in[25];
    const float* lb1 = (const float*)d_in[26];
    const float* lw2 = (const float*)d_in[27];
    const float* lb2 = (const float*)d_in[28];
    float* out = (float*)d_out;

    cudaFuncSetAttribute(fused_kernel, cudaFuncAttributeMaxDynamicSharedMemorySize,
                         FUSED_SMEM_BYTES);

    prep_kernel<<<16, 256>>>(lw0, lw1, lw2, lb0, lb1, lb2, out);
    fused_kernel<<<DGRID, DB, FUSED_SMEM_BYTES>>>(
        lm, lv, Tin,
        cw0, cb0, cw1, cb1, cw2, cb2,
        pw0, pb0, pw1, pb1, pw2, pb2,
        fmw1, fmb1, fmw2, fmb2,
        fvw1, fvb1, fvw2, fvb2,
        lb0, out);
}